// round 11
// baseline (speedup 1.0000x reference)
#include <cuda_runtime.h>
#include <math.h>
#include <stdint.h>

// ---------------- problem constants ----------------
#define BS    64
#define NSEG  3
#define SLEN  256
#define B3    192
#define TT    768
#define EDIM  300
#define HDIM  512
#define G3    1536
#define NNODE 18
#define NFEAT 600
#define NHID  600
#define NOUT  1024
#define BN    1152

// persistent GRU geometry
#define NKG   16
#define NBG   9
#define NSLOT 24

// output layout (floats)
#define OUT_RFTS 0UL
#define OUT_EMBS 25165824UL
#define OUT_MSKS 39911424UL
#define OUT_SG   39960576UL
#define OUT_HIDS 41140224UL

// GRU smem layout (floats)
#define WPK_FLOATS 49152
#define A_STRIDE   68
#define A0_OFF     WPK_FLOATS
#define A1_OFF     (A0_OFF + 32*A_STRIDE)
#define GHS_OFF    (A1_OFF + 32*A_STRIDE)
#define GHS_STRIDE 100
#define BSH_OFF    (GHS_OFF + 32*GHS_STRIDE)
#define SMEM_FLOATS (BSH_OFF + 96)
#define GRU_SMEM_BYTES (SMEM_FLOATS * 4)   // 227200 B

// xi smem layout (words)
#define YBM 64
#define XASTR 36
#define XACH (YBM * XASTR)          // 2304
#define XBSTR 132
#define XI_AS_WORDS (10 * XACH)     // 23040
#define XI_BS_WORDS (32 * XBSTR)    // 4224
#define XI_SMEM_BYTES ((XI_AS_WORDS + XI_BS_WORDS + 64) * 4)   // 109312

// ---------------- scratch ----------------
__device__ float g_xi[(size_t)B3 * SLEN * G3];
__device__ float g_h[2][B3 * HDIM];
__device__ float g_wihT[EDIM * G3];
__device__ float g_t1[BN * NHID];
__device__ float g_h1[BN * NHID];
__device__ float g_t2[BN * NOUT];
__device__ int   g_len[B3];
__device__ int   g_off[B3];
__device__ int   g_tlen[BS];
__device__ int   g_gmax[NBG];
__device__ int   g_bar_cnt[NBG];
__device__ int   g_bar_gen[NBG];
__device__ int   g_bmap[NBG * NSLOT];

// ---------------- helpers ----------------
__device__ __forceinline__ uint32_t tf32c(float x) {
    uint32_t u; asm("cvt.rna.tf32.f32 %0, %1;" : "=r"(u) : "f"(x)); return u;
}
__device__ __forceinline__ void mma8(float* d, uint32_t a0, uint32_t a1,
                                     uint32_t a2, uint32_t a3,
                                     uint32_t b0, uint32_t b1) {
    asm volatile(
        "mma.sync.aligned.m16n8k8.row.col.f32.tf32.tf32.f32 "
        "{%0,%1,%2,%3}, {%4,%5,%6,%7}, {%8,%9}, {%0,%1,%2,%3};"
        : "+f"(d[0]), "+f"(d[1]), "+f"(d[2]), "+f"(d[3])
        : "r"(a0), "r"(a1), "r"(a2), "r"(a3), "r"(b0), "r"(b1));
}

// ---------------- prep ----------------
__global__ void prep_kernel(const int* __restrict__ lens) {
    __shared__ int s_len[B3];
    __shared__ int hist[257];
    __shared__ int sorted_b[B3];
    int tid = threadIdx.x;

    for (int i = tid; i < 257; i += 256) hist[i] = 0;
    for (int i = tid; i < NBG * NSLOT; i += 256) g_bmap[i] = -1;
    if (tid < NBG) { g_bar_cnt[tid] = 0; g_bar_gen[tid] = 0; g_gmax[tid] = 0; }
    __syncthreads();

    if (tid < B3) {
        int l = lens[tid];
        s_len[tid] = l;
        g_len[tid] = l;
        atomicAdd(&hist[l], 1);
        int bb = tid / NSEG, s = tid % NSEG;
        int off = 0;
        for (int s2 = 0; s2 < s; s2++) off += lens[bb * NSEG + s2];
        g_off[tid] = off;
        if (s == 0)
            g_tlen[bb] = lens[bb*NSEG] + lens[bb*NSEG+1] + lens[bb*NSEG+2];
    }
    __syncthreads();
    if (tid == 0) {
        int acc = 0;
        for (int v = 1; v <= 256; v++) { int c = hist[v]; hist[v] = acc; acc += c; }
    }
    __syncthreads();
    if (tid < B3) {
        int pos = atomicAdd(&hist[s_len[tid]], 1);
        sorted_b[B3 - 1 - pos] = tid;
    }
    __syncthreads();
    if (tid < B3) {
        int i = tid;
        int b = sorted_b[i];
        int p = i % (2 * NBG);
        int g = (p < NBG) ? p : (2 * NBG - 1 - p);
        int slot = 2 * (i / (2 * NBG)) + ((p >= NBG) ? 1 : 0);
        g_bmap[g * NSLOT + slot] = b;
        atomicMax(&g_gmax[g], s_len[b]);
    }
    __syncthreads();
    if (tid < NBG) {
        int* gm = &g_bmap[tid * NSLOT];
        for (int i = 1; i < NSLOT; i++) {
            int b = gm[i];
            int l = (b >= 0) ? s_len[b] : -1;
            int j = i - 1;
            while (j >= 0) {
                int bj = gm[j];
                int lj = (bj >= 0) ? s_len[bj] : -1;
                if (lj < l) { gm[j + 1] = bj; j--; } else break;
            }
            gm[j + 1] = b;
        }
    }
}

__global__ void zero_h_kernel() {
    int i = blockIdx.x * blockDim.x + threadIdx.x;
    if (i < B3 * HDIM) g_h[0][i] = 0.f;
}

__global__ void transpose_wih_kernel(const float* __restrict__ w_ih) {
    for (int idx = blockIdx.x * blockDim.x + threadIdx.x;
         idx < EDIM * G3; idx += gridDim.x * blockDim.x) {
        int e = idx / G3, g = idx % G3;
        g_wihT[idx] = w_ih[g * EDIM + e];
    }
}

// ---------------- xi GEMM: A-resident tf32 mma ----------------
// Grid (2, 768): blockIdx.x = n-half (768 cols), blockIdx.y = 64-row tile.
// A (64x320, tf32) staged once; 6 n-tiles of 128 looped with reg-prefetched B.
__global__ __launch_bounds__(256, 2)
void xi_mma_kernel(const int* __restrict__ inds, const float* __restrict__ emb,
                   const float* __restrict__ b_ih) {
    extern __shared__ uint32_t XS[];
    uint32_t* As = XS;
    uint32_t* Bs = XS + XI_AS_WORDS;
    int* toksh = (int*)(XS + XI_AS_WORDS + XI_BS_WORDS);

    const int half = blockIdx.x;
    const int tr = blockIdx.y * YBM;
    const int b3 = tr >> 8, t0 = tr & 255;
    if (t0 >= g_len[b3]) return;

    const int tid = threadIdx.x, lane = tid & 31, wid = tid >> 5;
    const int mi = wid & 3, nj = wid >> 2;

    if (tid < YBM) toksh[tid] = inds[tr + tid];
    __syncthreads();

    // stage all A chunks once
    {
        const int arow = tid >> 2, aec = (tid & 3) * 8;
        const float* ep = emb + (size_t)toksh[arow] * EDIM;
        for (int ch = 0; ch < 10; ch++) {
#pragma unroll
            for (int i = 0; i < 2; i++) {
                int e = ch * 32 + aec + 4 * i;
                float4 v = make_float4(0.f, 0.f, 0.f, 0.f);
                if (e + 3 < EDIM) v = *(const float4*)(ep + e);
                else {
                    if (e     < EDIM) v.x = ep[e];
                    if (e + 1 < EDIM) v.y = ep[e + 1];
                    if (e + 2 < EDIM) v.z = ep[e + 2];
                    if (e + 3 < EDIM) v.w = ep[e + 3];
                }
                uint4 u;
                u.x = tf32c(v.x); u.y = tf32c(v.y); u.z = tf32c(v.z); u.w = tf32c(v.w);
                *(uint4*)&As[ch * XACH + arow * XASTR + aec + 4 * i] = u;
            }
        }
    }
    __syncthreads();

    const int bes = tid >> 3, bn4 = (tid & 7) * 16;

    // prefetch B phase 0 (j=0, ch=0; e=bes < 300 always)
    float4 pb[4];
    {
        const float* bp = g_wihT + (size_t)bes * G3 + half * 768 + bn4;
#pragma unroll
        for (int i = 0; i < 4; i++) pb[i] = *(const float4*)(bp + 4 * i);
    }

    for (int j = 0; j < 6; j++) {
        const int n0 = half * 768 + j * 128;
        float d[8][4];
#pragma unroll
        for (int nt = 0; nt < 8; nt++)
#pragma unroll
            for (int q = 0; q < 4; q++) d[nt][q] = 0.f;

        for (int ch = 0; ch < 10; ch++) {
            // store prefetched B
#pragma unroll
            for (int i = 0; i < 4; i++) {
                uint4 u;
                u.x = tf32c(pb[i].x); u.y = tf32c(pb[i].y);
                u.z = tf32c(pb[i].z); u.w = tf32c(pb[i].w);
                *(uint4*)&Bs[bes * XBSTR + bn4 + 4 * i] = u;
            }
            __syncthreads();
            // prefetch next phase
            {
                int jn = j, chn = ch + 1;
                if (chn == 10) { jn = j + 1; chn = 0; }
                if (jn < 6) {
                    int e = chn * 32 + bes;
                    bool ev = e < EDIM;
                    const float* bp = g_wihT + (size_t)e * G3 + half * 768 + jn * 128 + bn4;
#pragma unroll
                    for (int i = 0; i < 4; i++)
                        pb[i] = ev ? *(const float4*)(bp + 4 * i)
                                   : make_float4(0.f, 0.f, 0.f, 0.f);
                }
            }
            // mma
#pragma unroll
            for (int ks = 0; ks < 4; ks++) {
                const uint32_t* ab = As + ch * XACH + (16 * mi + (lane >> 2)) * XASTR + ks * 8 + (lane & 3);
                uint32_t a0 = ab[0];
                uint32_t a1 = ab[8 * XASTR];
                uint32_t a2 = ab[4];
                uint32_t a3 = ab[8 * XASTR + 4];
                const uint32_t* bb = Bs + (ks * 8 + (lane & 3)) * XBSTR + nj * 64 + (lane >> 2);
#pragma unroll
                for (int nt = 0; nt < 8; nt++)
                    mma8(d[nt], a0, a1, a2, a3, bb[nt * 8], bb[4 * XBSTR + nt * 8]);
            }
            __syncthreads();
        }
        // epilogue for this n-tile
        const int r0 = tr + 16 * mi + (lane >> 2);
        const int r1 = r0 + 8;
#pragma unroll
        for (int nt = 0; nt < 8; nt++) {
            int cg = n0 + nj * 64 + nt * 8 + 2 * (lane & 3);
            float2 bias = *(const float2*)&b_ih[cg];
            float2 v0 = make_float2(d[nt][0] + bias.x, d[nt][1] + bias.y);
            float2 v1 = make_float2(d[nt][2] + bias.x, d[nt][3] + bias.y);
            *(float2*)&g_xi[(size_t)r0 * G3 + cg] = v0;
            *(float2*)&g_xi[(size_t)r1 * G3 + cg] = v1;
        }
    }
}

// ---------------- persistent GRU: warp-specialized tf32 mma ----------------
// Warps 0-3: mma (warp nj computes m32 x n24); warps 4-7: h staging.
__global__ __launch_bounds__(256, 1)
void gru_mma_kernel(const float* __restrict__ w_hh, const float* __restrict__ b_hh,
                    float* __restrict__ out) {
    extern __shared__ float S[];
    uint32_t* Wu  = (uint32_t*)S;
    uint32_t* Au0 = (uint32_t*)(S + A0_OFF);
    uint32_t* Au1 = (uint32_t*)(S + A1_OFF);
    float*    ghs = S + GHS_OFF;
    float*    bsh = S + BSH_OFF;
    __shared__ int sb3[32];
    __shared__ int slen[32];
    __shared__ int srow[32];

    const int kg = blockIdx.x, bg = blockIdx.y;
    const int tid = threadIdx.x, lane = tid & 31, wid = tid >> 5;
    const bool stg = (wid >= 4);
    const int nj = wid & 3;                 // mma warps: n-block
    const int g4 = lane >> 2, tg = lane & 3;

    if (tid < 32) {
        int b = (tid < NSLOT) ? g_bmap[bg * NSLOT + tid] : -1;
        sb3[tid] = b;
        slen[tid] = (b >= 0) ? g_len[b] : 0;
        srow[tid] = (b >= 0) ? ((b / NSEG) * TT + g_off[b]) : 0;
    }
    if (tid < 96) {
        int kc = tid / 3, g = tid - 3 * (tid / 3);
        bsh[tid] = b_hh[g * HDIM + kg * 32 + kc];
    }
    // W pack (B-fragment order) — verified
    for (int i = tid; i < WPK_FLOATS; i += 256) {
        int p = i >> 1, half = i & 1;
        int l  = p & 31;
        int tq = p >> 5;
        int t  = tq % 3;
        int qn = tq / 3;
        int q  = qn & 63;
        int njj = qn >> 6;
        int e  = 8 * q + (l & 3) + 4 * half;
        int c  = 8 * t + (l >> 2);
        int kc = 8 * njj + c / 3;
        int g  = c - 3 * (c / 3);
        float v = w_hh[(size_t)(g * HDIM + kg * 32 + kc) * HDIM + e];
        Wu[i] = tf32c(v);
    }
    __syncthreads();

    const int gmax = g_gmax[bg];
    const int hmax1 = slen[16];

    // staging thread mapping (warps 4-7): 32 rows x 4 e-octets of 16
    const int srowS = (tid & 127) >> 2;
    const int soct  = tid & 3;
    const int sbb = sb3[srowS];
    const bool sval = stg && (sbb >= 0);

    // epilogue state in registers
    int   e_s[4], e_kc[4], e_b3[4], e_len[4], e_row[4];
    float hold[4];
#pragma unroll
    for (int it = 0; it < 4; it++) {
        int item = tid + it * 256;
        e_s[it] = item >> 5; e_kc[it] = item & 31;
        e_b3[it] = sb3[e_s[it]];
        e_len[it] = slen[e_s[it]];
        e_row[it] = srow[e_s[it]];
        hold[it] = 0.f;
    }

    for (int t = 0; t < gmax; t++) {
        const float* __restrict__ hc = g_h[t & 1];
        float* __restrict__ hn = g_h[(t + 1) & 1];
        const bool act1 = (t < hmax1);

        const float* hrow = sval ? (hc + (size_t)sbb * HDIM) : hc;

        // xi prefetch (all threads; overlaps MMA phase)
        float xiv[4][3];
#pragma unroll
        for (int it = 0; it < 4; it++) {
            xiv[it][0] = xiv[it][1] = xiv[it][2] = 0.f;
            if (e_b3[it] >= 0 && t < e_len[it]) {
                const float* xp = g_xi + ((size_t)e_b3[it] * SLEN + t) * G3 + kg * 32 + e_kc[it];
                xiv[it][0] = xp[0];
                xiv[it][1] = xp[HDIM];
                xiv[it][2] = xp[2 * HDIM];
            }
        }

        float4 pv[4];
        if (stg) {
            if (sval) {
                const float4* hp = (const float4*)(hrow + soct * 16);
#pragma unroll
                for (int i = 0; i < 4; i++) pv[i] = hp[i];
            } else {
#pragma unroll
                for (int i = 0; i < 4; i++) pv[i] = make_float4(0.f,0.f,0.f,0.f);
            }
            // store chunk 0 -> buf0
            uint32_t* ap = Au0 + srowS * A_STRIDE + soct * 16;
#pragma unroll
            for (int i = 0; i < 4; i++) {
                uint4 u;
                u.x = tf32c(pv[i].x); u.y = tf32c(pv[i].y);
                u.z = tf32c(pv[i].z); u.w = tf32c(pv[i].w);
                *(uint4*)(ap + 4 * i) = u;
            }
        }
        __syncthreads();

        float d[2][3][4];
#pragma unroll
        for (int m = 0; m < 2; m++)
#pragma unroll
            for (int gg = 0; gg < 3; gg++)
#pragma unroll
                for (int q = 0; q < 4; q++) d[m][gg][q] = 0.f;

#pragma unroll
        for (int ch = 0; ch < 8; ch++) {
            if (stg) {
                if (ch < 7) {
                    if (sval) {
                        const float4* hp = (const float4*)(hrow + (ch + 1) * 64 + soct * 16);
#pragma unroll
                        for (int i = 0; i < 4; i++) pv[i] = hp[i];
                    }
                    uint32_t* Adst = ((ch + 1) & 1) ? Au1 : Au0;
                    uint32_t* ap = Adst + srowS * A_STRIDE + soct * 16;
#pragma unroll
                    for (int i = 0; i < 4; i++) {
                        uint4 u;
                        u.x = tf32c(pv[i].x); u.y = tf32c(pv[i].y);
                        u.z = tf32c(pv[i].z); u.w = tf32c(pv[i].w);
                        *(uint4*)(ap + 4 * i) = u;
                    }
                }
            } else {
                const uint32_t* Abuf = (ch & 1) ? Au1 : Au0;
#pragma unroll
                for (int ql = 0; ql < 8; ql++) {
                    const uint32_t* ab = Abuf + g4 * A_STRIDE + ql * 8 + tg;
                    uint32_t a0 = ab[0];
                    uint32_t a1 = ab[8 * A_STRIDE];
                    uint32_t a2 = ab[4];
                    uint32_t a3 = ab[8 * A_STRIDE + 4];
                    int q = ch * 8 + ql;
                    const uint2* wp = (const uint2*)Wu + ((nj * 64 + q) * 3) * 32 + lane;
                    uint2 bf0 = wp[0];
                    uint2 bf1 = wp[32];
                    uint2 bf2 = wp[64];
                    mma8(d[0][0], a0, a1, a2, a3, bf0.x, bf0.y);
                    mma8(d[0][1], a0, a1, a2, a3, bf1.x, bf1.y);
                    mma8(d[0][2], a0, a1, a2, a3, bf2.x, bf2.y);
                    if (act1) {
                        const uint32_t* ab2 = ab + 16 * A_STRIDE;
                        uint32_t c0 = ab2[0];
                        uint32_t c1 = ab2[8 * A_STRIDE];
                        uint32_t c2 = ab2[4];
                        uint32_t c3 = ab2[8 * A_STRIDE + 4];
                        mma8(d[1][0], c0, c1, c2, c3, bf0.x, bf0.y);
                        mma8(d[1][1], c0, c1, c2, c3, bf1.x, bf1.y);
                        mma8(d[1][2], c0, c1, c2, c3, bf2.x, bf2.y);
                    }
                }
            }
            __syncthreads();
        }

        // dump (mma warps only)
        if (!stg) {
#pragma unroll
            for (int m = 0; m < 2; m++) {
                if (m == 1 && !act1) break;
                int r0 = (16 * m + g4) * GHS_STRIDE;
                int r1 = (16 * m + 8 + g4) * GHS_STRIDE;
                int nb = 24 * nj + 2 * tg;
                ghs[r0 + nb]      = d[m][0][0]; ghs[r0 + nb + 1]  = d[m][0][1];
                ghs[r1 + nb]      = d[m][0][2]; ghs[r1 + nb + 1]  = d[m][0][3];
                ghs[r0 + nb + 8]  = d[m][1][0]; ghs[r0 + nb + 9]  = d[m][1][1];
                ghs[r1 + nb + 8]  = d[m][1][2]; ghs[r1 + nb + 9]  = d[m][1][3];
                ghs[r0 + nb + 16] = d[m][2][0]; ghs[r0 + nb + 17] = d[m][2][1];
                ghs[r1 + nb + 16] = d[m][2][2]; ghs[r1 + nb + 17] = d[m][2][3];
            }
        }
        __syncthreads();

        // epilogue (all threads)
#pragma unroll
        for (int it = 0; it < 4; it++) {
            int b3 = e_b3[it];
            if (b3 < 0) continue;
            int kglob = kg * 32 + e_kc[it];
            float hv = hold[it];
            if (t < e_len[it]) {
                int s = e_s[it], kc = e_kc[it];
                float gr = ghs[s * GHS_STRIDE + 3 * kc + 0];
                float gz = ghs[s * GHS_STRIDE + 3 * kc + 1];
                float gn = ghs[s * GHS_STRIDE + 3 * kc + 2];
                float rr = 1.f / (1.f + expf(-(xiv[it][0] + gr + bsh[3 * kc])));
                float zz = 1.f / (1.f + expf(-(xiv[it][1] + gz + bsh[3 * kc + 1])));
                float nn = tanhf(xiv[it][2] + rr * (gn + bsh[3 * kc + 2]));
                hv = (1.f - zz) * nn + zz * hold[it];
                out[OUT_RFTS + (size_t)(e_row[it] + t) * HDIM + kglob] = hv;
            }
            hold[it] = hv;
            hn[(size_t)b3 * HDIM + kglob] = hv;
        }

        // inter-CTA barrier
        __threadfence();
        __syncthreads();
        if (tid == 0) {
            int a = atomicAdd(&g_bar_cnt[bg], 1);
            if (a == NKG - 1) {
                atomicExch(&g_bar_cnt[bg], 0);
                __threadfence();
                atomicExch(&g_bar_gen[bg], t + 1);
            } else {
                const volatile int* gv = (const volatile int*)&g_bar_gen[bg];
                while (*gv <= t) { }
                __threadfence();
            }
        }
        __syncthreads();
    }

    // final hidden states
#pragma unroll
    for (int it = 0; it < 4; it++) {
        if (e_b3[it] >= 0)
            out[OUT_HIDS + (size_t)e_b3[it] * HDIM + kg * 32 + e_kc[it]] = hold[it];
    }
}

// ---------------- packing & masks ----------------
__global__ void msks_kernel(float* __restrict__ out) {
    int b = blockIdx.x, t = threadIdx.x;
    out[OUT_MSKS + (size_t)b * TT + t] = (t < g_tlen[b]) ? 1.f : 0.f;
}

__global__ void pack_emb_kernel(const int* __restrict__ inds,
                                const float* __restrict__ emb,
                                float* __restrict__ out) {
    int t = blockIdx.x, b3 = blockIdx.y;
    if (t >= g_len[b3]) return;
    int tok = inds[b3 * SLEN + t];
    size_t row = (size_t)(b3 / 3) * TT + g_off[b3] + t;
    if (threadIdx.x < 75) {
        float4 v = *(const float4*)(emb + (size_t)tok * EDIM + threadIdx.x * 4);
        *(float4*)(out + OUT_EMBS + row * EDIM + threadIdx.x * 4) = v;
    }
}

// ---------------- GCN GEMM ----------------
__global__ __launch_bounds__(256)
void gemm64_kernel(const float* __restrict__ A, const float* __restrict__ B,
                   float* __restrict__ C, int M, int N, int K) {
    const int BK = 8;
    int m0 = blockIdx.y * 64, n0 = blockIdx.x * 64;
    __shared__ float As[BK * 64];
    __shared__ float Bs[BK * 64];
    int tid = threadIdx.x;
    int tx = tid & 15, ty = tid >> 4;

    float acc[4][4];
#pragma unroll
    for (int i = 0; i < 4; i++)
#pragma unroll
        for (int j = 0; j < 4; j++) acc[i][j] = 0.f;

    for (int k0 = 0; k0 < K; k0 += BK) {
#pragma unroll
        for (int i = 0; i < 2; i++) {
            int idx = tid + i * 256;
            int r = idx / BK, e = idx % BK;
            float v = 0.f;
            if (m0 + r < M) v = A[(size_t)(m0 + r) * K + k0 + e];
            As[e * 64 + r] = v;
        }
#pragma unroll
        for (int i = 0; i < 2; i++) {
            int idx = tid + i * 256;
            int e = idx >> 6, n = idx & 63;
            float v = 0.f;
            if (n0 + n < N) v = B[(size_t)(k0 + e) * N + n0 + n];
            Bs[e * 64 + n] = v;
        }
        __syncthreads();
#pragma unroll
        for (int e = 0; e < BK; e++) {
            float4 a = *(const float4*)&As[e * 64 + ty * 4];
            float4 b = *(const float4*)&Bs[e * 64 + tx * 4];
            acc[0][0] = fmaf(a.x, b.x, acc[0][0]); acc[0][1] = fmaf(a.x, b.y, acc[0][1]);
            acc[0][2] = fmaf(a.x, b.z, acc[0][2]); acc[0][3] = fmaf(a.x, b.w, acc[0][3]);
            acc[1][0] = fmaf(a.y, b.x, acc[1][0]); acc[1][1] = fmaf(a.y, b.y, acc[1][1]);
            acc[1][2] = fmaf(a.y, b.z, acc[1][2]); acc[1][3] = fmaf(a.y, b.w, acc[1][3]);
            acc[2][0] = fmaf(a.z, b.x, acc[2][0]); acc[2][1] = fmaf(a.z, b.y, acc[2][1]);
            acc[2][2] = fmaf(a.z, b.z, acc[2][2]); acc[2][3] = fmaf(a.z, b.w, acc[2][3]);
            acc[3][0] = fmaf(a.w, b.x, acc[3][0]); acc[3][1] = fmaf(a.w, b.y, acc[3][1]);
            acc[3][2] = fmaf(a.w, b.z, acc[3][2]); acc[3][3] = fmaf(a.w, b.w, acc[3][3]);
        }
        __syncthreads();
    }
#pragma unroll
    for (int i = 0; i < 4; i++) {
        int rg = m0 + ty * 4 + i;
        if (rg >= M) continue;
#pragma unroll
        for (int j = 0; j < 4; j++) {
            int cg = n0 + tx * 4 + j;
            if (cg < N) C[(size_t)rg * N + cg] = acc[i][j];
        }
    }
}

__global__ void adjmul_kernel(const float* __restrict__ adj, const float* __restrict__ X,
                              const float* __restrict__ bias, float* __restrict__ Y,
                              int F, int relu) {
    int total = BS * NNODE * F;
    for (int idx = blockIdx.x * blockDim.x + threadIdx.x; idx < total;
         idx += gridDim.x * blockDim.x) {
        int f = idx % F;
        int n = (idx / F) % NNODE;
        int b = idx / (F * NNODE);
        const float* Xb = X + (size_t)(b * NNODE) * F;
        const float* ad = adj + (size_t)(b * NNODE + n) * NNODE;
        float acc = bias[f];
#pragma unroll
        for (int m = 0; m < NNODE; m++)
            acc = fmaf(ad[m], Xb[(size_t)m * F + f], acc);
        if (relu) acc = fmaxf(acc, 0.f);
        Y[idx] = acc;
    }
}

// ---------------- host ----------------
extern "C" void kernel_launch(void* const* d_in, const int* in_sizes, int n_in,
                              void* d_out, int out_size) {
    const int*   inds = (const int*)  d_in[0];
    const int*   lens = (const int*)  d_in[1];
    const float* emb  = (const float*)d_in[2];
    const float* w_ih = (const float*)d_in[3];
    const float* w_hh = (const float*)d_in[4];
    const float* b_ih = (const float*)d_in[5];
    const float* b_hh = (const float*)d_in[6];
    const float* sg_x = (const float*)d_in[7];
    const float* adj  = (const float*)d_in[8];
    const float* gw1  = (const float*)d_in[9];
    const float* gb1  = (const float*)d_in[10];
    const float* gw2  = (const float*)d_in[11];
    const float* gb2  = (const float*)d_in[12];
    float* out = (float*)d_out;

    cudaFuncSetAttribute(gru_mma_kernel,
                         cudaFuncAttributeMaxDynamicSharedMemorySize, GRU_SMEM_BYTES);
    cudaFuncSetAttribute(xi_mma_kernel,
                         cudaFuncAttributeMaxDynamicSharedMemorySize, XI_SMEM_BYTES);

    cudaMemsetAsync(d_out, 0, (size_t)out_size * sizeof(float), 0);
    zero_h_kernel<<<(B3 * HDIM + 511) / 512, 512>>>();
    prep_kernel<<<1, 256>>>(lens);
    transpose_wih_kernel<<<512, 256>>>(w_ih);

    xi_mma_kernel<<<dim3(2, (B3 * SLEN) / YBM), 256, XI_SMEM_BYTES>>>(inds, emb, b_ih);

    msks_kernel<<<BS, TT>>>(out);
    pack_emb_kernel<<<dim3(SLEN, B3), 96>>>(inds, emb, out);

    gru_mma_kernel<<<dim3(NKG, NBG), 256, GRU_SMEM_BYTES>>>(w_hh, b_hh, out);

    // GCN
    gemm64_kernel<<<dim3((NHID + 63) / 64, (BN + 63) / 64), 256>>>(sg_x, gw1, g_t1, BN, NHID, NFEAT);
    adjmul_kernel<<<1350, 512>>>(adj, g_t1, gb1, g_h1, NHID, 1);
    gemm64_kernel<<<dim3((NOUT + 63) / 64, (BN + 63) / 64), 256>>>(g_h1, gw2, g_t2, BN, NOUT, NHID);
    adjmul_kernel<<<2304, 512>>>(adj, g_t2, gb2, out + OUT_SG, NOUT, 0);
}

// round 12
// speedup vs baseline: 1.0882x; 1.0882x over previous
#include <cuda_runtime.h>
#include <math.h>
#include <stdint.h>

// ---------------- problem constants ----------------
#define BS    64
#define NSEG  3
#define SLEN  256
#define B3    192
#define TT    768
#define EDIM  300
#define HDIM  512
#define G3    1536
#define NNODE 18
#define NFEAT 600
#define NHID  600
#define NOUT  1024
#define BN    1152

// persistent GRU geometry
#define NKG   16
#define NBG   9
#define NSLOT 24

// output layout (floats)
#define OUT_RFTS 0UL
#define OUT_EMBS 25165824UL
#define OUT_MSKS 39911424UL
#define OUT_SG   39960576UL
#define OUT_HIDS 41140224UL

// GRU smem layout (floats)
#define WPK_FLOATS 49152
#define A_STRIDE   68
#define A0_OFF     WPK_FLOATS
#define A1_OFF     (A0_OFF + 32*A_STRIDE)
#define GHS_OFF    (A1_OFF + 32*A_STRIDE)
#define GHS_STRIDE 100
#define BSH_OFF    (GHS_OFF + 32*GHS_STRIDE)
#define SMEM_FLOATS (BSH_OFF + 96)
#define GRU_SMEM_BYTES (SMEM_FLOATS * 4)   // 227200 B

// xi tiling
#define YBM 64
#define XASTR 36
#define XBSTR_E 36

// ---------------- scratch ----------------
__device__ float g_xi[(size_t)B3 * SLEN * G3];
__device__ float g_h[2][B3 * HDIM];
__device__ float g_t1[BN * NHID];
__device__ float g_h1[BN * NHID];
__device__ float g_t2[BN * NOUT];
__device__ int   g_len[B3];
__device__ int   g_off[B3];
__device__ int   g_tlen[BS];
__device__ int   g_gmax[NBG];
__device__ int   g_bar_cnt[NBG];
__device__ int   g_bar_gen[NBG];
__device__ int   g_bmap[NBG * NSLOT];

// ---------------- helpers ----------------
__device__ __forceinline__ uint32_t tf32c(float x) {
    uint32_t u; asm("cvt.rna.tf32.f32 %0, %1;" : "=r"(u) : "f"(x)); return u;
}
__device__ __forceinline__ void mma8(float* d, uint32_t a0, uint32_t a1,
                                     uint32_t a2, uint32_t a3,
                                     uint32_t b0, uint32_t b1) {
    asm volatile(
        "mma.sync.aligned.m16n8k8.row.col.f32.tf32.tf32.f32 "
        "{%0,%1,%2,%3}, {%4,%5,%6,%7}, {%8,%9}, {%0,%1,%2,%3};"
        : "+f"(d[0]), "+f"(d[1]), "+f"(d[2]), "+f"(d[3])
        : "r"(a0), "r"(a1), "r"(a2), "r"(a3), "r"(b0), "r"(b1));
}
__device__ __forceinline__ void ldsm4(uint32_t& r0, uint32_t& r1,
                                      uint32_t& r2, uint32_t& r3, uint32_t addr) {
    asm volatile("ldmatrix.sync.aligned.m8n8.x4.shared.b16 {%0,%1,%2,%3}, [%4];"
                 : "=r"(r0), "=r"(r1), "=r"(r2), "=r"(r3) : "r"(addr));
}

// ---------------- prep ----------------
__global__ void prep_kernel(const int* __restrict__ lens) {
    __shared__ int s_len[B3];
    __shared__ int hist[257];
    __shared__ int sorted_b[B3];
    int tid = threadIdx.x;

    for (int i = tid; i < 257; i += 256) hist[i] = 0;
    for (int i = tid; i < NBG * NSLOT; i += 256) g_bmap[i] = -1;
    if (tid < NBG) { g_bar_cnt[tid] = 0; g_bar_gen[tid] = 0; g_gmax[tid] = 0; }
    __syncthreads();

    if (tid < B3) {
        int l = lens[tid];
        s_len[tid] = l;
        g_len[tid] = l;
        atomicAdd(&hist[l], 1);
        int bb = tid / NSEG, s = tid % NSEG;
        int off = 0;
        for (int s2 = 0; s2 < s; s2++) off += lens[bb * NSEG + s2];
        g_off[tid] = off;
        if (s == 0)
            g_tlen[bb] = lens[bb*NSEG] + lens[bb*NSEG+1] + lens[bb*NSEG+2];
    }
    __syncthreads();
    if (tid == 0) {
        int acc = 0;
        for (int v = 1; v <= 256; v++) { int c = hist[v]; hist[v] = acc; acc += c; }
    }
    __syncthreads();
    if (tid < B3) {
        int pos = atomicAdd(&hist[s_len[tid]], 1);
        sorted_b[B3 - 1 - pos] = tid;
    }
    __syncthreads();
    if (tid < B3) {
        int i = tid;
        int b = sorted_b[i];
        int p = i % (2 * NBG);
        int g = (p < NBG) ? p : (2 * NBG - 1 - p);
        int slot = 2 * (i / (2 * NBG)) + ((p >= NBG) ? 1 : 0);
        g_bmap[g * NSLOT + slot] = b;
        atomicMax(&g_gmax[g], s_len[b]);
    }
    __syncthreads();
    if (tid < NBG) {
        int* gm = &g_bmap[tid * NSLOT];
        for (int i = 1; i < NSLOT; i++) {
            int b = gm[i];
            int l = (b >= 0) ? s_len[b] : -1;
            int j = i - 1;
            while (j >= 0) {
                int bj = gm[j];
                int lj = (bj >= 0) ? s_len[bj] : -1;
                if (lj < l) { gm[j + 1] = bj; j--; } else break;
            }
            gm[j + 1] = b;
        }
    }
}

__global__ void zero_h_kernel() {
    int i = blockIdx.x * blockDim.x + threadIdx.x;
    if (i < B3 * HDIM) g_h[0][i] = 0.f;
}

// ---------------- xi GEMM: tf32 mma + ldmatrix (A and B frags) ----------------
// Grid (12, 768): 128-col n-tiles, 64-row tiles. B staged [n][e] from w_ih directly.
__global__ __launch_bounds__(256, 2)
void xi_mma_kernel(const int* __restrict__ inds, const float* __restrict__ emb,
                   const float* __restrict__ w_ih, const float* __restrict__ b_ih) {
    __shared__ uint32_t As[YBM * XASTR];
    __shared__ uint32_t Bs[128 * XBSTR_E];
    __shared__ int toksh[YBM];

    const int tr = blockIdx.y * YBM;
    const int n0 = blockIdx.x * 128;
    const int b3 = tr >> 8, t0 = tr & 255;
    if (t0 >= g_len[b3]) return;

    const int tid = threadIdx.x, lane = tid & 31, wid = tid >> 5;
    const int mi = wid & 3, nj = wid >> 2;     // mi: 4 row-tiles of 16; nj: 2 col-tiles of 64

    if (tid < YBM) toksh[tid] = inds[tr + tid];
    __syncthreads();

    float d[8][4];
#pragma unroll
    for (int nt = 0; nt < 8; nt++)
#pragma unroll
        for (int q = 0; q < 4; q++) d[nt][q] = 0.f;

    const int arow = tid >> 2, aec = (tid & 3) * 8;
    const int brow = tid >> 1, beh = (tid & 1) * 16;

    const uint32_t abase = (uint32_t)__cvta_generic_to_shared(
        &As[(16 * mi + (lane & 15)) * XASTR + (lane >> 4) * 4]);
    const uint32_t bbase = (uint32_t)__cvta_generic_to_shared(
        &Bs[(nj * 64 + (lane & 7) + 8 * (lane >> 4)) * XBSTR_E + ((lane >> 3) & 1) * 4]);

    for (int ch = 0; ch < 10; ch++) {
        const int e0 = ch * 32;
        // stage A: 64 rows x 32 e (gathered, tf32)
        {
            const float* ep = emb + (size_t)toksh[arow] * EDIM;
#pragma unroll
            for (int i = 0; i < 2; i++) {
                int e = e0 + aec + 4 * i;
                float4 v = make_float4(0.f, 0.f, 0.f, 0.f);
                if (e + 3 < EDIM) v = *(const float4*)(ep + e);
                else {
                    if (e     < EDIM) v.x = ep[e];
                    if (e + 1 < EDIM) v.y = ep[e + 1];
                    if (e + 2 < EDIM) v.z = ep[e + 2];
                    if (e + 3 < EDIM) v.w = ep[e + 3];
                }
                uint4 u;
                u.x = tf32c(v.x); u.y = tf32c(v.y); u.z = tf32c(v.z); u.w = tf32c(v.w);
                *(uint4*)&As[arow * XASTR + aec + 4 * i] = u;
            }
        }
        // stage B: 128 n-rows x 32 e, straight from w_ih [g][e]
        {
            const float* bp = w_ih + (size_t)(n0 + brow) * EDIM;
#pragma unroll
            for (int i = 0; i < 4; i++) {
                int e = e0 + beh + 4 * i;
                float4 v = make_float4(0.f, 0.f, 0.f, 0.f);
                if (e + 3 < EDIM) v = *(const float4*)(bp + e);
                else {
                    if (e     < EDIM) v.x = bp[e];
                    if (e + 1 < EDIM) v.y = bp[e + 1];
                    if (e + 2 < EDIM) v.z = bp[e + 2];
                    if (e + 3 < EDIM) v.w = bp[e + 3];
                }
                uint4 u;
                u.x = tf32c(v.x); u.y = tf32c(v.y); u.z = tf32c(v.z); u.w = tf32c(v.w);
                *(uint4*)&Bs[brow * XBSTR_E + beh + 4 * i] = u;
            }
        }
        __syncthreads();
#pragma unroll
        for (int ks = 0; ks < 4; ks++) {
            uint32_t a0, a1, a2, a3;
            ldsm4(a0, a1, a2, a3, abase + ks * 32);
#pragma unroll
            for (int ntp = 0; ntp < 4; ntp++) {
                uint32_t r0, r1, r2, r3;
                ldsm4(r0, r1, r2, r3, bbase + (ntp * 16 * XBSTR_E + ks * 8) * 4);
                mma8(d[2 * ntp],     a0, a1, a2, a3, r0, r1);
                mma8(d[2 * ntp + 1], a0, a1, a2, a3, r2, r3);
            }
        }
        __syncthreads();
    }
    // epilogue
    const int r0 = tr + 16 * mi + (lane >> 2);
    const int r1 = r0 + 8;
#pragma unroll
    for (int nt = 0; nt < 8; nt++) {
        int cg = n0 + nj * 64 + nt * 8 + 2 * (lane & 3);
        float2 bias = *(const float2*)&b_ih[cg];
        float2 v0 = make_float2(d[nt][0] + bias.x, d[nt][1] + bias.y);
        float2 v1 = make_float2(d[nt][2] + bias.x, d[nt][3] + bias.y);
        *(float2*)&g_xi[(size_t)r0 * G3 + cg] = v0;
        *(float2*)&g_xi[(size_t)r1 * G3 + cg] = v1;
    }
}

// ---------------- persistent GRU: tf32 mma + ldmatrix, R8 skeleton ----------------
__global__ __launch_bounds__(256, 1)
void gru_mma_kernel(const float* __restrict__ w_hh, const float* __restrict__ b_hh,
                    float* __restrict__ out) {
    extern __shared__ float S[];
    uint32_t* Wu  = (uint32_t*)S;
    uint32_t* Au0 = (uint32_t*)(S + A0_OFF);
    uint32_t* Au1 = (uint32_t*)(S + A1_OFF);
    float*    ghs = S + GHS_OFF;
    float*    bsh = S + BSH_OFF;
    __shared__ int sb3[32];
    __shared__ int slen[32];
    __shared__ int srow[32];

    const int kg = blockIdx.x, bg = blockIdx.y;
    const int tid = threadIdx.x, lane = tid & 31, wid = tid >> 5;
    const int mi = wid & 1, nj = wid >> 1;
    const int g4 = lane >> 2, tg = lane & 3;

    if (tid < 32) {
        int b = (tid < NSLOT) ? g_bmap[bg * NSLOT + tid] : -1;
        sb3[tid] = b;
        slen[tid] = (b >= 0) ? g_len[b] : 0;
        srow[tid] = (b >= 0) ? ((b / NSEG) * TT + g_off[b]) : 0;
    }
    if (tid < 96) {
        int kc = tid / 3, g = tid - 3 * (tid / 3);
        bsh[tid] = b_hh[g * HDIM + kg * 32 + kc];
    }
    // W pack: uint4 = (b0(q), b1(q), b0(q+1), b1(q+1)) per (nj, q-pair, gate, lane)
    for (int i = tid; i < WPK_FLOATS; i += 256) {
        int w = i & 3;
        int v = i >> 2;
        int l = v & 31;
        int rest = v >> 5;
        int t = rest % 3;
        int u = rest / 3;
        int qh = u & 31;
        int njj = u >> 5;
        int q = 2 * qh + (w >> 1);
        int half = w & 1;
        int e = 8 * q + (l & 3) + 4 * half;
        int c = 8 * t + (l >> 2);
        int kc = 8 * njj + c / 3;
        int g = c - 3 * (c / 3);
        Wu[i] = tf32c(w_hh[(size_t)(g * HDIM + kg * 32 + kc) * HDIM + e]);
    }
    __syncthreads();

    const int gmax = g_gmax[bg];
    const int hmax1 = slen[16];
    const int srowS = tid >> 3;
    const int soct  = tid & 7;

    const int sbb = sb3[srowS];
    const bool sval = (sbb >= 0);

    const uint32_t abase0 = (uint32_t)__cvta_generic_to_shared(
        &Au0[(16 * mi + (lane & 15)) * A_STRIDE + (lane >> 4) * 4]);
    const uint32_t abase1 = (uint32_t)__cvta_generic_to_shared(
        &Au1[(16 * mi + (lane & 15)) * A_STRIDE + (lane >> 4) * 4]);

    int   e_s[4], e_kc[4], e_b3[4], e_len[4], e_row[4];
    float hold[4];
#pragma unroll
    for (int it = 0; it < 4; it++) {
        int item = tid + it * 256;
        e_s[it] = item >> 5; e_kc[it] = item & 31;
        e_b3[it] = sb3[e_s[it]];
        e_len[it] = slen[e_s[it]];
        e_row[it] = srow[e_s[it]];
        hold[it] = 0.f;
    }

    for (int t = 0; t < gmax; t++) {
        const float* __restrict__ hc = g_h[t & 1];
        float* __restrict__ hn = g_h[(t + 1) & 1];
        const bool act = (mi == 0) || (t < hmax1);

        const float* hrow = sval ? (hc + (size_t)sbb * HDIM) : hc;

        float4 pv0, pv1;
        if (sval) {
            const float4* hp = (const float4*)(hrow + soct * 8);
            pv0 = hp[0]; pv1 = hp[1];
        } else { pv0 = pv1 = make_float4(0.f,0.f,0.f,0.f); }

        // xi prefetch (overlaps MMA phase)
        float xiv[4][3];
#pragma unroll
        for (int it = 0; it < 4; it++) {
            xiv[it][0] = xiv[it][1] = xiv[it][2] = 0.f;
            if (e_b3[it] >= 0 && t < e_len[it]) {
                const float* xp = g_xi + ((size_t)e_b3[it] * SLEN + t) * G3 + kg * 32 + e_kc[it];
                xiv[it][0] = xp[0];
                xiv[it][1] = xp[HDIM];
                xiv[it][2] = xp[2 * HDIM];
            }
        }

        {
            uint4 u0, u1;
            u0.x = tf32c(pv0.x); u0.y = tf32c(pv0.y); u0.z = tf32c(pv0.z); u0.w = tf32c(pv0.w);
            u1.x = tf32c(pv1.x); u1.y = tf32c(pv1.y); u1.z = tf32c(pv1.z); u1.w = tf32c(pv1.w);
            uint32_t* ap = Au0 + srowS * A_STRIDE + soct * 8;
            *(uint4*)ap = u0;
            *(uint4*)(ap + 4) = u1;
        }
        __syncthreads();

        float d0[4] = {0,0,0,0}, d1[4] = {0,0,0,0}, d2[4] = {0,0,0,0};

#pragma unroll
        for (int ch = 0; ch < 8; ch++) {
            if (ch < 7 && sval) {
                const float4* hp = (const float4*)(hrow + (ch + 1) * 64 + soct * 8);
                pv0 = hp[0]; pv1 = hp[1];
            }
            if (act) {
                const uint32_t ab = (ch & 1) ? abase1 : abase0;
#pragma unroll
                for (int qh4 = 0; qh4 < 4; qh4++) {
                    uint32_t a0, a1, a2, a3, c0, c1, c2, c3;
                    ldsm4(a0, a1, a2, a3, ab + (qh4 * 2) * 32);
                    ldsm4(c0, c1, c2, c3, ab + (qh4 * 2 + 1) * 32);
                    int qq = ch * 4 + qh4;
                    const uint4* wp = (const uint4*)Wu + ((nj * 32 + qq) * 3) * 32 + lane;
                    uint4 f0 = wp[0];
                    uint4 f1 = wp[32];
                    uint4 f2 = wp[64];
                    mma8(d0, a0, a1, a2, a3, f0.x, f0.y);
                    mma8(d1, a0, a1, a2, a3, f1.x, f1.y);
                    mma8(d2, a0, a1, a2, a3, f2.x, f2.y);
                    mma8(d0, c0, c1, c2, c3, f0.z, f0.w);
                    mma8(d1, c0, c1, c2, c3, f1.z, f1.w);
                    mma8(d2, c0, c1, c2, c3, f2.z, f2.w);
                }
            }
            if (ch < 7) {
                uint4 u0, u1;
                u0.x = tf32c(pv0.x); u0.y = tf32c(pv0.y); u0.z = tf32c(pv0.z); u0.w = tf32c(pv0.w);
                u1.x = tf32c(pv1.x); u1.y = tf32c(pv1.y); u1.z = tf32c(pv1.z); u1.w = tf32c(pv1.w);
                uint32_t* Adst = ((ch + 1) & 1) ? Au1 : Au0;
                uint32_t* ap = Adst + srowS * A_STRIDE + soct * 8;
                *(uint4*)ap = u0;
                *(uint4*)(ap + 4) = u1;
            }
            __syncthreads();
        }

        if (act) {
            int r0 = (16 * mi + g4) * GHS_STRIDE;
            int r1 = (16 * mi + 8 + g4) * GHS_STRIDE;
            int nb = 24 * nj + 2 * tg;
            ghs[r0 + nb]      = d0[0]; ghs[r0 + nb + 1]  = d0[1];
            ghs[r1 + nb]      = d0[2]; ghs[r1 + nb + 1]  = d0[3];
            ghs[r0 + nb + 8]  = d1[0]; ghs[r0 + nb + 9]  = d1[1];
            ghs[r1 + nb + 8]  = d1[2]; ghs[r1 + nb + 9]  = d1[3];
            ghs[r0 + nb + 16] = d2[0]; ghs[r0 + nb + 17] = d2[1];
            ghs[r1 + nb + 16] = d2[2]; ghs[r1 + nb + 17] = d2[3];
        }
        __syncthreads();

#pragma unroll
        for (int it = 0; it < 4; it++) {
            int b3 = e_b3[it];
            if (b3 < 0) continue;
            int kglob = kg * 32 + e_kc[it];
            float hv = hold[it];
            if (t < e_len[it]) {
                int s = e_s[it], kc = e_kc[it];
                float gr = ghs[s * GHS_STRIDE + 3 * kc + 0];
                float gz = ghs[s * GHS_STRIDE + 3 * kc + 1];
                float gn = ghs[s * GHS_STRIDE + 3 * kc + 2];
                float rr = 1.f / (1.f + expf(-(xiv[it][0] + gr + bsh[3 * kc])));
                float zz = 1.f / (1.f + expf(-(xiv[it][1] + gz + bsh[3 * kc + 1])));
                float nn = tanhf(xiv[it][2] + rr * (gn + bsh[3 * kc + 2]));
                hv = (1.f - zz) * nn + zz * hold[it];
                out[OUT_RFTS + (size_t)(e_row[it] + t) * HDIM + kglob] = hv;
            }
            hold[it] = hv;
            hn[(size_t)b3 * HDIM + kglob] = hv;
        }

        __threadfence();
        __syncthreads();
        if (tid == 0) {
            int a = atomicAdd(&g_bar_cnt[bg], 1);
            if (a == NKG - 1) {
                atomicExch(&g_bar_cnt[bg], 0);
                __threadfence();
                atomicExch(&g_bar_gen[bg], t + 1);
            } else {
                const volatile int* gv = (const volatile int*)&g_bar_gen[bg];
                while (*gv <= t) { }
                __threadfence();
            }
        }
        __syncthreads();
    }

#pragma unroll
    for (int it = 0; it < 4; it++) {
        if (e_b3[it] >= 0)
            out[OUT_HIDS + (size_t)e_b3[it] * HDIM + kg * 32 + e_kc[it]] = hold[it];
    }
}

// ---------------- packing & masks ----------------
__global__ void msks_kernel(float* __restrict__ out) {
    int b = blockIdx.x, t = threadIdx.x;
    out[OUT_MSKS + (size_t)b * TT + t] = (t < g_tlen[b]) ? 1.f : 0.f;
}

__global__ void pack_emb_kernel(const int* __restrict__ inds,
                                const float* __restrict__ emb,
                                float* __restrict__ out) {
    int t = blockIdx.x, b3 = blockIdx.y;
    if (t >= g_len[b3]) return;
    int tok = inds[b3 * SLEN + t];
    size_t row = (size_t)(b3 / 3) * TT + g_off[b3] + t;
    if (threadIdx.x < 75) {
        float4 v = *(const float4*)(emb + (size_t)tok * EDIM + threadIdx.x * 4);
        *(float4*)(out + OUT_EMBS + row * EDIM + threadIdx.x * 4) = v;
    }
}

// ---------------- GCN GEMM ----------------
__global__ __launch_bounds__(256)
void gemm64_kernel(const float* __restrict__ A, const float* __restrict__ B,
                   float* __restrict__ C, int M, int N, int K) {
    const int BK = 8;
    int m0 = blockIdx.y * 64, n0 = blockIdx.x * 64;
    __shared__ float As[BK * 64];
    __shared__ float Bs[BK * 64];
    int tid = threadIdx.x;
    int tx = tid & 15, ty = tid >> 4;

    float acc[4][4];
#pragma unroll
    for (int i = 0; i < 4; i++)
#pragma unroll
        for (int j = 0; j < 4; j++) acc[i][j] = 0.f;

    for (int k0 = 0; k0 < K; k0 += BK) {
#pragma unroll
        for (int i = 0; i < 2; i++) {
            int idx = tid + i * 256;
            int r = idx / BK, e = idx % BK;
            float v = 0.f;
            if (m0 + r < M) v = A[(size_t)(m0 + r) * K + k0 + e];
            As[e * 64 + r] = v;
        }
#pragma unroll
        for (int i = 0; i < 2; i++) {
            int idx = tid + i * 256;
            int e = idx >> 6, n = idx & 63;
            float v = 0.f;
            if (n0 + n < N) v = B[(size_t)(k0 + e) * N + n0 + n];
            Bs[e * 64 + n] = v;
        }
        __syncthreads();
#pragma unroll
        for (int e = 0; e < BK; e++) {
            float4 a = *(const float4*)&As[e * 64 + ty * 4];
            float4 b = *(const float4*)&Bs[e * 64 + tx * 4];
            acc[0][0] = fmaf(a.x, b.x, acc[0][0]); acc[0][1] = fmaf(a.x, b.y, acc[0][1]);
            acc[0][2] = fmaf(a.x, b.z, acc[0][2]); acc[0][3] = fmaf(a.x, b.w, acc[0][3]);
            acc[1][0] = fmaf(a.y, b.x, acc[1][0]); acc[1][1] = fmaf(a.y, b.y, acc[1][1]);
            acc[1][2] = fmaf(a.y, b.z, acc[1][2]); acc[1][3] = fmaf(a.y, b.w, acc[1][3]);
            acc[2][0] = fmaf(a.z, b.x, acc[2][0]); acc[2][1] = fmaf(a.z, b.y, acc[2][1]);
            acc[2][2] = fmaf(a.z, b.z, acc[2][2]); acc[2][3] = fmaf(a.z, b.w, acc[2][3]);
            acc[3][0] = fmaf(a.w, b.x, acc[3][0]); acc[3][1] = fmaf(a.w, b.y, acc[3][1]);
            acc[3][2] = fmaf(a.w, b.z, acc[3][2]); acc[3][3] = fmaf(a.w, b.w, acc[3][3]);
        }
        __syncthreads();
    }
#pragma unroll
    for (int i = 0; i < 4; i++) {
        int rg = m0 + ty * 4 + i;
        if (rg >= M) continue;
#pragma unroll
        for (int j = 0; j < 4; j++) {
            int cg = n0 + tx * 4 + j;
            if (cg < N) C[(size_t)rg * N + cg] = acc[i][j];
        }
    }
}

__global__ void adjmul_kernel(const float* __restrict__ adj, const float* __restrict__ X,
                              const float* __restrict__ bias, float* __restrict__ Y,
                              int F, int relu) {
    int total = BS * NNODE * F;
    for (int idx = blockIdx.x * blockDim.x + threadIdx.x; idx < total;
         idx += gridDim.x * blockDim.x) {
        int f = idx % F;
        int n = (idx / F) % NNODE;
        int b = idx / (F * NNODE);
        const float* Xb = X + (size_t)(b * NNODE) * F;
        const float* ad = adj + (size_t)(b * NNODE + n) * NNODE;
        float acc = bias[f];
#pragma unroll
        for (int m = 0; m < NNODE; m++)
            acc = fmaf(ad[m], Xb[(size_t)m * F + f], acc);
        if (relu) acc = fmaxf(acc, 0.f);
        Y[idx] = acc;
    }
}

// ---------------- host ----------------
extern "C" void kernel_launch(void* const* d_in, const int* in_sizes, int n_in,
                              void* d_out, int out_size) {
    const int*   inds = (const int*)  d_in[0];
    const int*   lens = (const int*)  d_in[1];
    const float* emb  = (const float*)d_in[2];
    const float* w_ih = (const float*)d_in[3];
    const float* w_hh = (const float*)d_in[4];
    const float* b_ih = (const float*)d_in[5];
    const float* b_hh = (const float*)d_in[6];
    const float* sg_x = (const float*)d_in[7];
    const float* adj  = (const float*)d_in[8];
    const float* gw1  = (const float*)d_in[9];
    const float* gb1  = (const float*)d_in[10];
    const float* gw2  = (const float*)d_in[11];
    const float* gb2  = (const float*)d_in[12];
    float* out = (float*)d_out;

    cudaFuncSetAttribute(gru_mma_kernel,
                         cudaFuncAttributeMaxDynamicSharedMemorySize, GRU_SMEM_BYTES);

    cudaMemsetAsync(d_out, 0, (size_t)out_size * sizeof(float), 0);
    zero_h_kernel<<<(B3 * HDIM + 511) / 512, 512>>>();
    prep_kernel<<<1, 256>>>(lens);

    xi_mma_kernel<<<dim3(G3 / 128, (B3 * SLEN) / YBM), 256>>>(inds, emb, w_ih, b_ih);

    msks_kernel<<<BS, TT>>>(out);
    pack_emb_kernel<<<dim3(SLEN, B3), 96>>>(inds, emb, out);

    gru_mma_kernel<<<dim3(NKG, NBG), 256, GRU_SMEM_BYTES>>>(w_hh, b_hh, out);

    // GCN
    gemm64_kernel<<<dim3((NHID + 63) / 64, (BN + 63) / 64), 256>>>(sg_x, gw1, g_t1, BN, NHID, NFEAT);
    adjmul_kernel<<<1350, 512>>>(adj, g_t1, gb1, g_h1, NHID, 1);
    gemm64_kernel<<<dim3((NOUT + 63) / 64, (BN + 63) / 64), 256>>>(g_h1, gw2, g_t2, BN, NOUT, NHID);
    adjmul_kernel<<<2304, 512>>>(adj, g_t2, gb2, out + OUT_SG, NOUT, 0);
}

// round 14
// speedup vs baseline: 1.2744x; 1.1711x over previous
#include <cuda_runtime.h>
#include <cuda_fp16.h>
#include <math.h>
#include <stdint.h>

// ---------------- problem constants ----------------
#define BS    64
#define NSEG  3
#define SLEN  256
#define B3    192
#define TT    768
#define EDIM  300
#define HDIM  512
#define G3    1536
#define NNODE 18
#define NFEAT 600
#define NHID  600
#define NOUT  1024
#define BN    1152

// persistent GRU geometry
#define NKG   16
#define NBG   9
#define NSLOT 24

// output layout (floats)
#define OUT_RFTS 0UL
#define OUT_EMBS 25165824UL
#define OUT_MSKS 39911424UL
#define OUT_SG   39960576UL
#define OUT_HIDS 41140224UL

// GRU smem layout
#define W16_WORDS  24576            // 96 cols x 512 k fp16 = 24576 u32 words
#define H_OFF_W    24576            // u32-word offset of H buffer
#define H_STR_H    520              // halfs per h row (padded)
#define H_STR_W    260
#define GHS_OFF_F  (H_OFF_W + 32 * H_STR_W)   // 32896
#define GHS_STRIDE 100
#define BSH_OFF_F  (GHS_OFF_F + 32 * GHS_STRIDE)
#define GRU_SMEM_FLOATS (BSH_OFF_F + 96)
#define GRU_SMEM_BYTES (GRU_SMEM_FLOATS * 4)   // 144768 B

// xi tiling
#define YBM 64
#define XASTR 36
#define XBSTR_E 36

// ---------------- scratch ----------------
__device__ float g_xi[(size_t)B3 * SLEN * G3];
__device__ float g_h[2][B3 * HDIM];
__device__ float g_t1[BN * NHID];
__device__ float g_h1[BN * NHID];
__device__ float g_t2[BN * NOUT];
__device__ int   g_len[B3];
__device__ int   g_off[B3];
__device__ int   g_tlen[BS];
__device__ int   g_gmax[NBG];
__device__ int   g_bar_cnt[NBG];
__device__ int   g_bar_gen[NBG];
__device__ int   g_bmap[NBG * NSLOT];

// ---------------- helpers ----------------
__device__ __forceinline__ uint32_t tf32c(float x) {
    uint32_t u; asm("cvt.rna.tf32.f32 %0, %1;" : "=r"(u) : "f"(x)); return u;
}
__device__ __forceinline__ void mma8(float* d, uint32_t a0, uint32_t a1,
                                     uint32_t a2, uint32_t a3,
                                     uint32_t b0, uint32_t b1) {
    asm volatile(
        "mma.sync.aligned.m16n8k8.row.col.f32.tf32.tf32.f32 "
        "{%0,%1,%2,%3}, {%4,%5,%6,%7}, {%8,%9}, {%0,%1,%2,%3};"
        : "+f"(d[0]), "+f"(d[1]), "+f"(d[2]), "+f"(d[3])
        : "r"(a0), "r"(a1), "r"(a2), "r"(a3), "r"(b0), "r"(b1));
}
__device__ __forceinline__ void mma16(float* d, uint32_t a0, uint32_t a1,
                                      uint32_t a2, uint32_t a3,
                                      uint32_t b0, uint32_t b1) {
    asm volatile(
        "mma.sync.aligned.m16n8k16.row.col.f32.f16.f16.f32 "
        "{%0,%1,%2,%3}, {%4,%5,%6,%7}, {%8,%9}, {%0,%1,%2,%3};"
        : "+f"(d[0]), "+f"(d[1]), "+f"(d[2]), "+f"(d[3])
        : "r"(a0), "r"(a1), "r"(a2), "r"(a3), "r"(b0), "r"(b1));
}
__device__ __forceinline__ void ldsm4(uint32_t& r0, uint32_t& r1,
                                      uint32_t& r2, uint32_t& r3, uint32_t addr) {
    asm volatile("ldmatrix.sync.aligned.m8n8.x4.shared.b16 {%0,%1,%2,%3}, [%4];"
                 : "=r"(r0), "=r"(r1), "=r"(r2), "=r"(r3) : "r"(addr));
}
__device__ __forceinline__ uint32_t h2bits(float a, float b) {
    __half2 h = __floats2half2_rn(a, b);
    return *reinterpret_cast<uint32_t*>(&h);
}

// ---------------- prep ----------------
__global__ void prep_kernel(const int* __restrict__ lens) {
    __shared__ int s_len[B3];
    __shared__ int hist[257];
    __shared__ int sorted_b[B3];
    int tid = threadIdx.x;

    for (int i = tid; i < 257; i += 256) hist[i] = 0;
    for (int i = tid; i < NBG * NSLOT; i += 256) g_bmap[i] = -1;
    if (tid < NBG) { g_bar_cnt[tid] = 0; g_bar_gen[tid] = 0; g_gmax[tid] = 0; }
    __syncthreads();

    if (tid < B3) {
        int l = lens[tid];
        s_len[tid] = l;
        g_len[tid] = l;
        atomicAdd(&hist[l], 1);
        int bb = tid / NSEG, s = tid % NSEG;
        int off = 0;
        for (int s2 = 0; s2 < s; s2++) off += lens[bb * NSEG + s2];
        g_off[tid] = off;
        if (s == 0)
            g_tlen[bb] = lens[bb*NSEG] + lens[bb*NSEG+1] + lens[bb*NSEG+2];
    }
    __syncthreads();
    if (tid == 0) {
        int acc = 0;
        for (int v = 1; v <= 256; v++) { int c = hist[v]; hist[v] = acc; acc += c; }
    }
    __syncthreads();
    if (tid < B3) {
        int pos = atomicAdd(&hist[s_len[tid]], 1);
        sorted_b[B3 - 1 - pos] = tid;
    }
    __syncthreads();
    if (tid < B3) {
        int i = tid;
        int b = sorted_b[i];
        int p = i % (2 * NBG);
        int g = (p < NBG) ? p : (2 * NBG - 1 - p);
        int slot = 2 * (i / (2 * NBG)) + ((p >= NBG) ? 1 : 0);
        g_bmap[g * NSLOT + slot] = b;
        atomicMax(&g_gmax[g], s_len[b]);
    }
    __syncthreads();
    if (tid < NBG) {
        int* gm = &g_bmap[tid * NSLOT];
        for (int i = 1; i < NSLOT; i++) {
            int b = gm[i];
            int l = (b >= 0) ? s_len[b] : -1;
            int j = i - 1;
            while (j >= 0) {
                int bj = gm[j];
                int lj = (bj >= 0) ? s_len[bj] : -1;
                if (lj < l) { gm[j + 1] = bj; j--; } else break;
            }
            gm[j + 1] = b;
        }
    }
}

__global__ void zero_h_kernel() {
    int i = blockIdx.x * blockDim.x + threadIdx.x;
    if (i < B3 * HDIM) g_h[0][i] = 0.f;
}

// ---------------- xi GEMM: tf32 mma + ldmatrix (unchanged from R11) ----------------
__global__ __launch_bounds__(256, 2)
void xi_mma_kernel(const int* __restrict__ inds, const float* __restrict__ emb,
                   const float* __restrict__ w_ih, const float* __restrict__ b_ih) {
    __shared__ uint32_t As[YBM * XASTR];
    __shared__ uint32_t Bs[128 * XBSTR_E];
    __shared__ int toksh[YBM];

    const int tr = blockIdx.y * YBM;
    const int n0 = blockIdx.x * 128;
    const int b3 = tr >> 8, t0 = tr & 255;
    if (t0 >= g_len[b3]) return;

    const int tid = threadIdx.x, lane = tid & 31, wid = tid >> 5;
    const int mi = wid & 3, nj = wid >> 2;

    if (tid < YBM) toksh[tid] = inds[tr + tid];
    __syncthreads();

    float d[8][4];
#pragma unroll
    for (int nt = 0; nt < 8; nt++)
#pragma unroll
        for (int q = 0; q < 4; q++) d[nt][q] = 0.f;

    const int arow = tid >> 2, aec = (tid & 3) * 8;
    const int brow = tid >> 1, beh = (tid & 1) * 16;

    const uint32_t abase = (uint32_t)__cvta_generic_to_shared(
        &As[(16 * mi + (lane & 15)) * XASTR + (lane >> 4) * 4]);
    const uint32_t bbase = (uint32_t)__cvta_generic_to_shared(
        &Bs[(nj * 64 + (lane & 7) + 8 * (lane >> 4)) * XBSTR_E + ((lane >> 3) & 1) * 4]);

    for (int ch = 0; ch < 10; ch++) {
        const int e0 = ch * 32;
        {
            const float* ep = emb + (size_t)toksh[arow] * EDIM;
#pragma unroll
            for (int i = 0; i < 2; i++) {
                int e = e0 + aec + 4 * i;
                float4 v = make_float4(0.f, 0.f, 0.f, 0.f);
                if (e + 3 < EDIM) v = *(const float4*)(ep + e);
                else {
                    if (e     < EDIM) v.x = ep[e];
                    if (e + 1 < EDIM) v.y = ep[e + 1];
                    if (e + 2 < EDIM) v.z = ep[e + 2];
                    if (e + 3 < EDIM) v.w = ep[e + 3];
                }
                uint4 u;
                u.x = tf32c(v.x); u.y = tf32c(v.y); u.z = tf32c(v.z); u.w = tf32c(v.w);
                *(uint4*)&As[arow * XASTR + aec + 4 * i] = u;
            }
        }
        {
            const float* bp = w_ih + (size_t)(n0 + brow) * EDIM;
#pragma unroll
            for (int i = 0; i < 4; i++) {
                int e = e0 + beh + 4 * i;
                float4 v = make_float4(0.f, 0.f, 0.f, 0.f);
                if (e + 3 < EDIM) v = *(const float4*)(bp + e);
                else {
                    if (e     < EDIM) v.x = bp[e];
                    if (e + 1 < EDIM) v.y = bp[e + 1];
                    if (e + 2 < EDIM) v.z = bp[e + 2];
                    if (e + 3 < EDIM) v.w = bp[e + 3];
                }
                uint4 u;
                u.x = tf32c(v.x); u.y = tf32c(v.y); u.z = tf32c(v.z); u.w = tf32c(v.w);
                *(uint4*)&Bs[brow * XBSTR_E + beh + 4 * i] = u;
            }
        }
        __syncthreads();
#pragma unroll
        for (int ks = 0; ks < 4; ks++) {
            uint32_t a0, a1, a2, a3;
            ldsm4(a0, a1, a2, a3, abase + ks * 32);
#pragma unroll
            for (int ntp = 0; ntp < 4; ntp++) {
                uint32_t r0, r1, r2, r3;
                ldsm4(r0, r1, r2, r3, bbase + (ntp * 16 * XBSTR_E + ks * 8) * 4);
                mma8(d[2 * ntp],     a0, a1, a2, a3, r0, r1);
                mma8(d[2 * ntp + 1], a0, a1, a2, a3, r2, r3);
            }
        }
        __syncthreads();
    }
    const int r0 = tr + 16 * mi + (lane >> 2);
    const int r1 = r0 + 8;
#pragma unroll
    for (int nt = 0; nt < 8; nt++) {
        int cg = n0 + nj * 64 + nt * 8 + 2 * (lane & 3);
        float2 bias = *(const float2*)&b_ih[cg];
        float2 v0 = make_float2(d[nt][0] + bias.x, d[nt][1] + bias.y);
        float2 v1 = make_float2(d[nt][2] + bias.x, d[nt][3] + bias.y);
        *(float2*)&g_xi[(size_t)r0 * G3 + cg] = v0;
        *(float2*)&g_xi[(size_t)r1 * G3 + cg] = v1;
    }
}

// ---------------- persistent GRU: fp16 mma, full-h staging, acq/rel barrier ----------------
__global__ __launch_bounds__(256, 1)
void gru_mma_kernel(const float* __restrict__ w_hh, const float* __restrict__ b_hh,
                    float* __restrict__ out) {
    extern __shared__ float S[];
    uint32_t* Wu = (uint32_t*)S;                    // fp16 W, B-frag order
    uint16_t* Hh = (uint16_t*)(S + H_OFF_W);        // h tile [32][520] halfs
    uint32_t* Hw = (uint32_t*)Hh;
    float*    ghs = S + GHS_OFF_F;
    float*    bsh = S + BSH_OFF_F;
    __shared__ int sb3[32];
    __shared__ int slen[32];
    __shared__ int srow[32];

    const int kg = blockIdx.x, bg = blockIdx.y;
    const int tid = threadIdx.x, lane = tid & 31, wid = tid >> 5;
    const int mi = wid & 1, nj = wid >> 1;
    const int g4 = lane >> 2, tg = lane & 3;

    if (tid < 32) {
        int b = (tid < NSLOT) ? g_bmap[bg * NSLOT + tid] : -1;
        sb3[tid] = b;
        slen[tid] = (b >= 0) ? g_len[b] : 0;
        srow[tid] = (b >= 0) ? ((b / NSEG) * TT + g_off[b]) : 0;
    }
    if (tid < 96) {
        int kc = tid / 3, g = tid - 3 * (tid / 3);
        bsh[tid] = b_hh[g * HDIM + kg * 32 + kc];
    }
    // W pack fp16: u32 index i = (((nj*32+q)*3+t)*32 + l)*2 + w01
    for (int i = tid; i < W16_WORDS; i += 256) {
        int w01 = i & 1;
        int r = i >> 1;
        int l = r & 31;
        int t3 = (r >> 5) % 3;
        int qn = (r >> 5) / 3;
        int q = qn & 31;
        int njj = qn >> 5;
        int k = 16 * q + 2 * (l & 3) + 8 * w01;
        int c = 8 * t3 + (l >> 2);
        int kc = 8 * njj + c / 3;
        int g = c - 3 * (c / 3);
        const float* wp = w_hh + (size_t)(g * HDIM + kg * 32 + kc) * HDIM + k;
        Wu[i] = h2bits(wp[0], wp[1]);
    }
    __syncthreads();

    const int gmax = g_gmax[bg];
    const int hmax1 = slen[16];

    // staging: row = lane, warp wid covers halfs [64*wid, 64*wid+64)
    const int st_b3  = sb3[lane];
    const int st_len = slen[lane];

    // ldmatrix A base: lane -> (row, half) per m16n8k16 x4 pattern
    const uint32_t abase = (uint32_t)__cvta_generic_to_shared(
        Hh + (16 * mi + (lane & 7) + 8 * ((lane >> 3) & 1)) * H_STR_H + 8 * (lane >> 4));

    int   e_s[4], e_kc[4], e_b3[4], e_len[4], e_row[4];
    float hold[4];
#pragma unroll
    for (int it = 0; it < 4; it++) {
        int item = tid + it * 256;
        e_s[it] = item >> 5; e_kc[it] = item & 31;
        e_b3[it] = sb3[e_s[it]];
        e_len[it] = slen[e_s[it]];
        e_row[it] = srow[e_s[it]];
        hold[it] = 0.f;
    }

    int* const cntp = &g_bar_cnt[bg];
    int* const genp = &g_bar_gen[bg];

    for (int t = 0; t < gmax; t++) {
        const float* __restrict__ hc = g_h[t & 1];
        float* __restrict__ hn = g_h[(t + 1) & 1];
        const bool act = (mi == 0) || (t < hmax1);

        // xi prefetch (overlaps staging + MMA)
        float xiv[4][3];
#pragma unroll
        for (int it = 0; it < 4; it++) {
            xiv[it][0] = xiv[it][1] = xiv[it][2] = 0.f;
            if (e_b3[it] >= 0 && t < e_len[it]) {
                const float* xp = g_xi + ((size_t)e_b3[it] * SLEN + t) * G3 + kg * 32 + e_kc[it];
                xiv[it][0] = xp[0];
                xiv[it][1] = xp[HDIM];
                xiv[it][2] = xp[2 * HDIM];
            }
        }

        // stage h (live rows only) -> fp16 smem
        if (st_b3 >= 0 && t < st_len) {
            const float4* hp = (const float4*)(hc + (size_t)st_b3 * HDIM + wid * 64);
            float4 v[16];
#pragma unroll
            for (int j = 0; j < 16; j++) v[j] = hp[j];
            uint32_t* dst = Hw + lane * H_STR_W + wid * 32;
#pragma unroll
            for (int j = 0; j < 8; j++) {
                uint4 u;
                u.x = h2bits(v[2*j].x,   v[2*j].y);
                u.y = h2bits(v[2*j].z,   v[2*j].w);
                u.z = h2bits(v[2*j+1].x, v[2*j+1].y);
                u.w = h2bits(v[2*j+1].z, v[2*j+1].w);
                *(uint4*)(dst + 4 * j) = u;
            }
        }
        __syncthreads();

        float d[3][2][4];
#pragma unroll
        for (int g = 0; g < 3; g++)
#pragma unroll
            for (int p = 0; p < 2; p++)
#pragma unroll
                for (int q = 0; q < 4; q++) d[g][p][q] = 0.f;

        if (act) {
#pragma unroll
            for (int q = 0; q < 32; q++) {
                uint32_t a0, a1, a2, a3;
                ldsm4(a0, a1, a2, a3, abase + 32 * q);
                const uint2* wp = (const uint2*)Wu + ((nj * 32 + q) * 3) * 32 + lane;
                uint2 f0 = wp[0];
                uint2 f1 = wp[32];
                uint2 f2 = wp[64];
                const int p = q & 1;
                mma16(d[0][p], a0, a1, a2, a3, f0.x, f0.y);
                mma16(d[1][p], a0, a1, a2, a3, f1.x, f1.y);
                mma16(d[2][p], a0, a1, a2, a3, f2.x, f2.y);
            }
            int r0 = (16 * mi + g4) * GHS_STRIDE;
            int r1 = (16 * mi + 8 + g4) * GHS_STRIDE;
            int nb = 24 * nj + 2 * tg;
#pragma unroll
            for (int g = 0; g < 3; g++) {
                ghs[r0 + nb + 8 * g]     = d[g][0][0] + d[g][1][0];
                ghs[r0 + nb + 8 * g + 1] = d[g][0][1] + d[g][1][1];
                ghs[r1 + nb + 8 * g]     = d[g][0][2] + d[g][1][2];
                ghs[r1 + nb + 8 * g + 1] = d[g][0][3] + d[g][1][3];
            }
        }
        __syncthreads();

        // epilogue (live items only)
#pragma unroll
        for (int it = 0; it < 4; it++) {
            if (e_b3[it] < 0 || t >= e_len[it]) continue;
            int kglob = kg * 32 + e_kc[it];
            int s = e_s[it], kc = e_kc[it];
            float gr = ghs[s * GHS_STRIDE + 3 * kc + 0];
            float gz = ghs[s * GHS_STRIDE + 3 * kc + 1];
            float gn = ghs[s * GHS_STRIDE + 3 * kc + 2];
            float rr = 1.f / (1.f + expf(-(xiv[it][0] + gr + bsh[3 * kc])));
            float zz = 1.f / (1.f + expf(-(xiv[it][1] + gz + bsh[3 * kc + 1])));
            float nn = tanhf(xiv[it][2] + rr * (gn + bsh[3 * kc + 2]));
            float hv = (1.f - zz) * nn + zz * hold[it];
            hold[it] = hv;
            out[OUT_RFTS + (size_t)(e_row[it] + t) * HDIM + kglob] = hv;
            hn[(size_t)e_b3[it] * HDIM + kglob] = hv;
        }

        // inter-CTA barrier: release/acquire, no MEMBAR
        __syncthreads();
        if (tid == 0) {
            int a;
            asm volatile("atom.acq_rel.gpu.global.add.s32 %0, [%1], 1;"
                         : "=r"(a) : "l"(cntp) : "memory");
            if (a == NKG - 1) {
                asm volatile("st.relaxed.gpu.global.s32 [%0], %1;"
                             :: "l"(cntp), "r"(0) : "memory");
                asm volatile("st.release.gpu.global.s32 [%0], %1;"
                             :: "l"(genp), "r"(t + 1) : "memory");
            } else {
                int g;
                do {
                    asm volatile("ld.acquire.gpu.global.s32 %0, [%1];"
                                 : "=r"(g) : "l"(genp) : "memory");
                } while (g <= t);
            }
        }
        __syncthreads();
    }

#pragma unroll
    for (int it = 0; it < 4; it++) {
        if (e_b3[it] >= 0)
            out[OUT_HIDS + (size_t)e_b3[it] * HDIM + kg * 32 + e_kc[it]] = hold[it];
    }
}

// ---------------- packing & masks ----------------
__global__ void msks_kernel(float* __restrict__ out) {
    int b = blockIdx.x, t = threadIdx.x;
    out[OUT_MSKS + (size_t)b * TT + t] = (t < g_tlen[b]) ? 1.f : 0.f;
}

__global__ void pack_emb_kernel(const int* __restrict__ inds,
                                const float* __restrict__ emb,
                                float* __restrict__ out) {
    int t = blockIdx.x, b3 = blockIdx.y;
    if (t >= g_len[b3]) return;
    int tok = inds[b3 * SLEN + t];
    size_t row = (size_t)(b3 / 3) * TT + g_off[b3] + t;
    if (threadIdx.x < 75) {
        float4 v = *(const float4*)(emb + (size_t)tok * EDIM + threadIdx.x * 4);
        *(float4*)(out + OUT_EMBS + row * EDIM + threadIdx.x * 4) = v;
    }
}

// ---------------- GCN GEMM ----------------
__global__ __launch_bounds__(256)
void gemm64_kernel(const float* __restrict__ A, const float* __restrict__ B,
                   float* __restrict__ C, int M, int N, int K) {
    const int BK = 8;
    int m0 = blockIdx.y * 64, n0 = blockIdx.x * 64;
    __shared__ float As[BK * 64];
    __shared__ float Bs[BK * 64];
    int tid = threadIdx.x;
    int tx = tid & 15, ty = tid >> 4;

    float acc[4][4];
#pragma unroll
    for (int i = 0; i < 4; i++)
#pragma unroll
        for (int j = 0; j < 4; j++) acc[i][j] = 0.f;

    for (int k0 = 0; k0 < K; k0 += BK) {
#pragma unroll
        for (int i = 0; i < 2; i++) {
            int idx = tid + i * 256;
            int r = idx / BK, e = idx % BK;
            float v = 0.f;
            if (m0 + r < M) v = A[(size_t)(m0 + r) * K + k0 + e];
            As[e * 64 + r] = v;
        }
#pragma unroll
        for (int i = 0; i < 2; i++) {
            int idx = tid + i * 256;
            int e = idx >> 6, n = idx & 63;
            float v = 0.f;
            if (n0 + n < N) v = B[(size_t)(k0 + e) * N + n0 + n];
            Bs[e * 64 + n] = v;
        }
        __syncthreads();
#pragma unroll
        for (int e = 0; e < BK; e++) {
            float4 a = *(const float4*)&As[e * 64 + ty * 4];
            float4 b = *(const float4*)&Bs[e * 64 + tx * 4];
            acc[0][0] = fmaf(a.x, b.x, acc[0][0]); acc[0][1] = fmaf(a.x, b.y, acc[0][1]);
            acc[0][2] = fmaf(a.x, b.z, acc[0][2]); acc[0][3] = fmaf(a.x, b.w, acc[0][3]);
            acc[1][0] = fmaf(a.y, b.x, acc[1][0]); acc[1][1] = fmaf(a.y, b.y, acc[1][1]);
            acc[1][2] = fmaf(a.y, b.z, acc[1][2]); acc[1][3] = fmaf(a.y, b.w, acc[1][3]);
            acc[2][0] = fmaf(a.z, b.x, acc[2][0]); acc[2][1] = fmaf(a.z, b.y, acc[2][1]);
            acc[2][2] = fmaf(a.z, b.z, acc[2][2]); acc[2][3] = fmaf(a.z, b.w, acc[2][3]);
            acc[3][0] = fmaf(a.w, b.x, acc[3][0]); acc[3][1] = fmaf(a.w, b.y, acc[3][1]);
            acc[3][2] = fmaf(a.w, b.z, acc[3][2]); acc[3][3] = fmaf(a.w, b.w, acc[3][3]);
        }
        __syncthreads();
    }
#pragma unroll
    for (int i = 0; i < 4; i++) {
        int rg = m0 + ty * 4 + i;
        if (rg >= M) continue;
#pragma unroll
        for (int j = 0; j < 4; j++) {
            int cg = n0 + tx * 4 + j;
            if (cg < N) C[(size_t)rg * N + cg] = acc[i][j];
        }
    }
}

__global__ void adjmul_kernel(const float* __restrict__ adj, const float* __restrict__ X,
                              const float* __restrict__ bias, float* __restrict__ Y,
                              int F, int relu) {
    int total = BS * NNODE * F;
    for (int idx = blockIdx.x * blockDim.x + threadIdx.x; idx < total;
         idx += gridDim.x * blockDim.x) {
        int f = idx % F;
        int n = (idx / F) % NNODE;
        int b = idx / (F * NNODE);
        const float* Xb = X + (size_t)(b * NNODE) * F;
        const float* ad = adj + (size_t)(b * NNODE + n) * NNODE;
        float acc = bias[f];
#pragma unroll
        for (int m = 0; m < NNODE; m++)
            acc = fmaf(ad[m], Xb[(size_t)m * F + f], acc);
        if (relu) acc = fmaxf(acc, 0.f);
        Y[idx] = acc;
    }
}

// ---------------- host ----------------
extern "C" void kernel_launch(void* const* d_in, const int* in_sizes, int n_in,
                              void* d_out, int out_size) {
    const int*   inds = (const int*)  d_in[0];
    const int*   lens = (const int*)  d_in[1];
    const float* emb  = (const float*)d_in[2];
    const float* w_ih = (const float*)d_in[3];
    const float* w_hh = (const float*)d_in[4];
    const float* b_ih = (const float*)d_in[5];
    const float* b_hh = (const float*)d_in[6];
    const float* sg_x = (const float*)d_in[7];
    const float* adj  = (const float*)d_in[8];
    const float* gw1  = (const float*)d_in[9];
    const float* gb1  = (const float*)d_in[10];
    const float* gw2  = (const float*)d_in[11];
    const float* gb2  = (const float*)d_in[12];
    float* out = (float*)d_out;

    cudaFuncSetAttribute(gru_mma_kernel,
                         cudaFuncAttributeMaxDynamicSharedMemorySize, GRU_SMEM_BYTES);

    cudaMemsetAsync(d_out, 0, (size_t)out_size * sizeof(float), 0);
    zero_h_kernel<<<(B3 * HDIM + 511) / 512, 512>>>();
    prep_kernel<<<1, 256>>>(lens);

    xi_mma_kernel<<<dim3(G3 / 128, (B3 * SLEN) / YBM), 256>>>(inds, emb, w_ih, b_ih);

    msks_kernel<<<BS, TT>>>(out);
    pack_emb_kernel<<<dim3(SLEN, B3), 96>>>(inds, emb, out);

    gru_mma_kernel<<<dim3(NKG, NBG), 256, GRU_SMEM_BYTES>>>(w_hh, b_hh, out);

    // GCN
    gemm64_kernel<<<dim3((NHID + 63) / 64, (BN + 63) / 64), 256>>>(sg_x, gw1, g_t1, BN, NHID, NFEAT);
    adjmul_kernel<<<1350, 512>>>(adj, g_t1, gb1, g_h1, NHID, 1);
    gemm64_kernel<<<dim3((NOUT + 63) / 64, (BN + 63) / 64), 256>>>(g_h1, gw2, g_t2, BN, NOUT, NHID);
    adjmul_kernel<<<2304, 512>>>(adj, g_t2, gb2, out + OUT_SG, NOUT, 0);
}

// round 17
// speedup vs baseline: 1.2910x; 1.0130x over previous
#include <cuda_runtime.h>
#include <cuda_fp16.h>
#include <math.h>
#include <stdint.h>

// ---------------- problem constants ----------------
#define BS    64
#define NSEG  3
#define SLEN  256
#define B3    192
#define TT    768
#define EDIM  300
#define HDIM  512
#define G3    1536
#define NNODE 18
#define NFEAT 600
#define NHID  600
#define NOUT  1024
#define BN    1152

// persistent GRU geometry
#define NKG   16
#define NBG   9
#define NSLOT 24

// output layout (floats)
#define OUT_RFTS 0UL
#define OUT_EMBS 25165824UL
#define OUT_MSKS 39911424UL
#define OUT_SG   39960576UL
#define OUT_HIDS 41140224UL

// GRU smem layout (u32 words)
#define W16_WORDS  24576            // 96 cols x 512 k fp16
#define H_OFF_W    24576
#define H_STR_H    520
#define H_STR_W    260
#define GRU_SMEM_WORDS (H_OFF_W + 32 * H_STR_W)    // 32896
#define GRU_SMEM_BYTES (GRU_SMEM_WORDS * 4)        // 131584 B

// xi tiling
#define YBM 64
#define XASTR 36
#define XBSTR_E 36

// ---------------- scratch ----------------
__device__ float g_xi[(size_t)B3 * SLEN * G3];
__device__ float g_h[2][B3 * HDIM];
__device__ float g_t1[BN * NHID];
__device__ float g_h1[BN * NHID];
__device__ float g_t2[BN * NOUT];
__device__ int   g_len[B3];
__device__ int   g_off[B3];
__device__ int   g_tlen[BS];
__device__ int   g_gmax[NBG];
__device__ int   g_bar_cnt[NBG];
__device__ int   g_bar_gen[NBG];
__device__ int   g_bmap[NBG * NSLOT];

// ---------------- helpers ----------------
__device__ __forceinline__ uint32_t tf32c(float x) {
    uint32_t u; asm("cvt.rna.tf32.f32 %0, %1;" : "=r"(u) : "f"(x)); return u;
}
__device__ __forceinline__ void mma8(float* d, uint32_t a0, uint32_t a1,
                                     uint32_t a2, uint32_t a3,
                                     uint32_t b0, uint32_t b1) {
    asm volatile(
        "mma.sync.aligned.m16n8k8.row.col.f32.tf32.tf32.f32 "
        "{%0,%1,%2,%3}, {%4,%5,%6,%7}, {%8,%9}, {%0,%1,%2,%3};"
        : "+f"(d[0]), "+f"(d[1]), "+f"(d[2]), "+f"(d[3])
        : "r"(a0), "r"(a1), "r"(a2), "r"(a3), "r"(b0), "r"(b1));
}
__device__ __forceinline__ void mma16(float* d, uint32_t a0, uint32_t a1,
                                      uint32_t a2, uint32_t a3,
                                      uint32_t b0, uint32_t b1) {
    asm volatile(
        "mma.sync.aligned.m16n8k16.row.col.f32.f16.f16.f32 "
        "{%0,%1,%2,%3}, {%4,%5,%6,%7}, {%8,%9}, {%0,%1,%2,%3};"
        : "+f"(d[0]), "+f"(d[1]), "+f"(d[2]), "+f"(d[3])
        : "r"(a0), "r"(a1), "r"(a2), "r"(a3), "r"(b0), "r"(b1));
}
__device__ __forceinline__ void ldsm4(uint32_t& r0, uint32_t& r1,
                                      uint32_t& r2, uint32_t& r3, uint32_t addr) {
    asm volatile("ldmatrix.sync.aligned.m8n8.x4.shared.b16 {%0,%1,%2,%3}, [%4];"
                 : "=r"(r0), "=r"(r1), "=r"(r2), "=r"(r3) : "r"(addr));
}
__device__ __forceinline__ uint32_t h2bits(float a, float b) {
    __half2 h = __floats2half2_rn(a, b);
    return *reinterpret_cast<uint32_t*>(&h);
}
__device__ __forceinline__ float sigm_(float x) { return 1.f / (1.f + expf(-x)); }

// ---------------- prep ----------------
__global__ void prep_kernel(const int* __restrict__ lens) {
    __shared__ int s_len[B3];
    __shared__ int hist[257];
    __shared__ int sorted_b[B3];
    int tid = threadIdx.x;

    for (int i = tid; i < 257; i += 256) hist[i] = 0;
    for (int i = tid; i < NBG * NSLOT; i += 256) g_bmap[i] = -1;
    if (tid < NBG) { g_bar_cnt[tid] = 0; g_bar_gen[tid] = 0; g_gmax[tid] = 0; }
    __syncthreads();

    if (tid < B3) {
        int l = lens[tid];
        s_len[tid] = l;
        g_len[tid] = l;
        atomicAdd(&hist[l], 1);
        int bb = tid / NSEG, s = tid % NSEG;
        int off = 0;
        for (int s2 = 0; s2 < s; s2++) off += lens[bb * NSEG + s2];
        g_off[tid] = off;
        if (s == 0)
            g_tlen[bb] = lens[bb*NSEG] + lens[bb*NSEG+1] + lens[bb*NSEG+2];
    }
    __syncthreads();
    if (tid == 0) {
        int acc = 0;
        for (int v = 1; v <= 256; v++) { int c = hist[v]; hist[v] = acc; acc += c; }
    }
    __syncthreads();
    if (tid < B3) {
        int pos = atomicAdd(&hist[s_len[tid]], 1);
        sorted_b[B3 - 1 - pos] = tid;
    }
    __syncthreads();
    if (tid < B3) {
        int i = tid;
        int b = sorted_b[i];
        int p = i % (2 * NBG);
        int g = (p < NBG) ? p : (2 * NBG - 1 - p);
        int slot = 2 * (i / (2 * NBG)) + ((p >= NBG) ? 1 : 0);
        g_bmap[g * NSLOT + slot] = b;
        atomicMax(&g_gmax[g], s_len[b]);
    }
    __syncthreads();
    if (tid < NBG) {
        int* gm = &g_bmap[tid * NSLOT];
        for (int i = 1; i < NSLOT; i++) {
            int b = gm[i];
            int l = (b >= 0) ? s_len[b] : -1;
            int j = i - 1;
            while (j >= 0) {
                int bj = gm[j];
                int lj = (bj >= 0) ? s_len[bj] : -1;
                if (lj < l) { gm[j + 1] = bj; j--; } else break;
            }
            gm[j + 1] = b;
        }
    }
}

__global__ void zero_h_kernel() {
    int i = blockIdx.x * blockDim.x + threadIdx.x;
    if (i < B3 * HDIM) g_h[0][i] = 0.f;
}

// ---------------- xi GEMM: tf32 mma + ldmatrix ----------------
__global__ __launch_bounds__(256, 3)
void xi_mma_kernel(const int* __restrict__ inds, const float* __restrict__ emb,
                   const float* __restrict__ w_ih, const float* __restrict__ b_ih) {
    __shared__ uint32_t As[YBM * XASTR];
    __shared__ uint32_t Bs[128 * XBSTR_E];
    __shared__ int toksh[YBM];

    const int tr = blockIdx.y * YBM;
    const int n0 = blockIdx.x * 128;
    const int b3 = tr >> 8, t0 = tr & 255;
    if (t0 >= g_len[b3]) return;

    const int tid = threadIdx.x, lane = tid & 31, wid = tid >> 5;
    const int mi = wid & 3, nj = wid >> 2;

    if (tid < YBM) toksh[tid] = inds[tr + tid];
    __syncthreads();

    float d[8][4];
#pragma unroll
    for (int nt = 0; nt < 8; nt++)
#pragma unroll
        for (int q = 0; q < 4; q++) d[nt][q] = 0.f;

    const int arow = tid >> 2, aec = (tid & 3) * 8;
    const int brow = tid >> 1, beh = (tid & 1) * 16;

    const uint32_t abase = (uint32_t)__cvta_generic_to_shared(
        &As[(16 * mi + (lane & 15)) * XASTR + (lane >> 4) * 4]);
    const uint32_t bbase = (uint32_t)__cvta_generic_to_shared(
        &Bs[(nj * 64 + (lane & 7) + 8 * (lane >> 4)) * XBSTR_E + ((lane >> 3) & 1) * 4]);

    for (int ch = 0; ch < 10; ch++) {
        const int e0 = ch * 32;
        {
            const float* ep = emb + (size_t)toksh[arow] * EDIM;
#pragma unroll
            for (int i = 0; i < 2; i++) {
                int e = e0 + aec + 4 * i;
                float4 v = make_float4(0.f, 0.f, 0.f, 0.f);
                if (e + 3 < EDIM) v = *(const float4*)(ep + e);
                else {
                    if (e     < EDIM) v.x = ep[e];
                    if (e + 1 < EDIM) v.y = ep[e + 1];
                    if (e + 2 < EDIM) v.z = ep[e + 2];
                    if (e + 3 < EDIM) v.w = ep[e + 3];
                }
                uint4 u;
                u.x = tf32c(v.x); u.y = tf32c(v.y); u.z = tf32c(v.z); u.w = tf32c(v.w);
                *(uint4*)&As[arow * XASTR + aec + 4 * i] = u;
            }
        }
        {
            const float* bp = w_ih + (size_t)(n0 + brow) * EDIM;
#pragma unroll
            for (int i = 0; i < 4; i++) {
                int e = e0 + beh + 4 * i;
                float4 v = make_float4(0.f, 0.f, 0.f, 0.f);
                if (e + 3 < EDIM) v = *(const float4*)(bp + e);
                else {
                    if (e     < EDIM) v.x = bp[e];
                    if (e + 1 < EDIM) v.y = bp[e + 1];
                    if (e + 2 < EDIM) v.z = bp[e + 2];
                    if (e + 3 < EDIM) v.w = bp[e + 3];
                }
                uint4 u;
                u.x = tf32c(v.x); u.y = tf32c(v.y); u.z = tf32c(v.z); u.w = tf32c(v.w);
                *(uint4*)&Bs[brow * XBSTR_E + beh + 4 * i] = u;
            }
        }
        __syncthreads();
#pragma unroll
        for (int ks = 0; ks < 4; ks++) {
            uint32_t a0, a1, a2, a3;
            ldsm4(a0, a1, a2, a3, abase + ks * 32);
#pragma unroll
            for (int ntp = 0; ntp < 4; ntp++) {
                uint32_t r0, r1, r2, r3;
                ldsm4(r0, r1, r2, r3, bbase + (ntp * 16 * XBSTR_E + ks * 8) * 4);
                mma8(d[2 * ntp],     a0, a1, a2, a3, r0, r1);
                mma8(d[2 * ntp + 1], a0, a1, a2, a3, r2, r3);
            }
        }
        __syncthreads();
    }
    const int r0 = tr + 16 * mi + (lane >> 2);
    const int r1 = r0 + 8;
#pragma unroll
    for (int nt = 0; nt < 8; nt++) {
        int cg = n0 + nj * 64 + nt * 8 + 2 * (lane & 3);
        float2 bias = *(const float2*)&b_ih[cg];
        float2 v0 = make_float2(d[nt][0] + bias.x, d[nt][1] + bias.y);
        float2 v1 = make_float2(d[nt][2] + bias.x, d[nt][3] + bias.y);
        *(float2*)&g_xi[(size_t)r0 * G3 + cg] = v0;
        *(float2*)&g_xi[(size_t)r1 * G3 + cg] = v1;
    }
}

// ---------------- persistent GRU: fp16 mma, epilogue in registers ----------------
// W pack delivers gate g via f-register index, kc via B-frag column:
// lane holds d[g][*] = gate-g gh for (rows 16mi+g4, +8) x (kc 8nj+2tg, +1).
__global__ __launch_bounds__(256, 1)
void gru_mma_kernel(const float* __restrict__ w_hh, const float* __restrict__ b_hh,
                    float* __restrict__ out) {
    extern __shared__ float S[];
    uint32_t* Wu = (uint32_t*)S;
    uint16_t* Hh = (uint16_t*)(S + H_OFF_W);
    uint32_t* Hw = (uint32_t*)Hh;
    __shared__ int sb3[32];
    __shared__ int slen[32];
    __shared__ int srow[32];

    const int kg = blockIdx.x, bg = blockIdx.y;
    const int tid = threadIdx.x, lane = tid & 31, wid = tid >> 5;
    const int mi = wid & 1, nj = wid >> 1;
    const int g4 = lane >> 2, tg = lane & 3;

    if (tid < 32) {
        int b = (tid < NSLOT) ? g_bmap[bg * NSLOT + tid] : -1;
        sb3[tid] = b;
        slen[tid] = (b >= 0) ? g_len[b] : 0;
        srow[tid] = (b >= 0) ? ((b / NSEG) * TT + g_off[b]) : 0;
    }
    // W pack fp16: gate = f-register index, kc = 8*nj + (l>>2)
    for (int i = tid; i < W16_WORDS; i += 256) {
        int w01 = i & 1;
        int r = i >> 1;
        int l = r & 31;
        int t3 = (r >> 5) % 3;
        int qn = (r >> 5) / 3;
        int q = qn & 31;
        int njj = qn >> 5;
        int k = 16 * q + 2 * (l & 3) + 8 * w01;
        int kc = 8 * njj + (l >> 2);
        const float* wp = w_hh + (size_t)(t3 * HDIM + kg * 32 + kc) * HDIM + k;
        Wu[i] = h2bits(wp[0], wp[1]);
    }
    __syncthreads();

    const int gmax = g_gmax[bg];
    const int hmax1 = slen[16];

    // staging: row = lane, warp wid covers halfs [64*wid, 64*wid+64)
    const int st_b3  = sb3[lane];
    const int st_len = slen[lane];

    const uint32_t abase = (uint32_t)__cvta_generic_to_shared(
        Hh + (16 * mi + (lane & 7) + 8 * ((lane >> 3) & 1)) * H_STR_H + 8 * (lane >> 4));

    // per-lane epilogue ownership
    const int s0 = 16 * mi + g4, s1 = s0 + 8;
    const int kc0 = 8 * nj + 2 * tg;
    const int b30 = sb3[s0], b31 = sb3[s1];
    const int len0 = slen[s0], len1 = slen[s1];
    const int row0 = srow[s0], row1 = srow[s1];
    const int kglob = kg * 32 + kc0;
    float2 br_ = *(const float2*)(b_hh + kglob);
    float2 bz_ = *(const float2*)(b_hh + HDIM + kglob);
    float2 bn_ = *(const float2*)(b_hh + 2 * HDIM + kglob);
    float hold[4] = {0.f, 0.f, 0.f, 0.f};

    int* const cntp = &g_bar_cnt[bg];
    int* const genp = &g_bar_gen[bg];

    for (int t = 0; t < gmax; t++) {
        const float* __restrict__ hc = g_h[t & 1];
        float* __restrict__ hn = g_h[(t + 1) & 1];
        const bool act = (mi == 0) || (t < hmax1);
        const bool live0 = (b30 >= 0) && (t < len0);
        const bool live1 = (b31 >= 0) && (t < len1);

        // xi prefetch (overlaps staging + MMA)
        float2 xr0, xz0, xn0, xr1, xz1, xn1;
        if (live0) {
            const float* xp = g_xi + ((size_t)b30 * SLEN + t) * G3 + kglob;
            xr0 = *(const float2*)xp;
            xz0 = *(const float2*)(xp + HDIM);
            xn0 = *(const float2*)(xp + 2 * HDIM);
        }
        if (live1) {
            const float* xp = g_xi + ((size_t)b31 * SLEN + t) * G3 + kglob;
            xr1 = *(const float2*)xp;
            xz1 = *(const float2*)(xp + HDIM);
            xn1 = *(const float2*)(xp + 2 * HDIM);
        }

        // stage h (live rows only) -> fp16 smem
        if (st_b3 >= 0 && t < st_len) {
            const float4* hp = (const float4*)(hc + (size_t)st_b3 * HDIM + wid * 64);
            float4 v[16];
#pragma unroll
            for (int j = 0; j < 16; j++) v[j] = hp[j];
            uint32_t* dst = Hw + lane * H_STR_W + wid * 32;
#pragma unroll
            for (int j = 0; j < 8; j++) {
                uint4 u;
                u.x = h2bits(v[2*j].x,   v[2*j].y);
                u.y = h2bits(v[2*j].z,   v[2*j].w);
                u.z = h2bits(v[2*j+1].x, v[2*j+1].y);
                u.w = h2bits(v[2*j+1].z, v[2*j+1].w);
                *(uint4*)(dst + 4 * j) = u;
            }
        }
        __syncthreads();

        float d[3][2][4];
#pragma unroll
        for (int g = 0; g < 3; g++)
#pragma unroll
            for (int p = 0; p < 2; p++)
#pragma unroll
                for (int q = 0; q < 4; q++) d[g][p][q] = 0.f;

        if (act) {
#pragma unroll
            for (int q = 0; q < 32; q++) {
                uint32_t a0, a1, a2, a3;
                ldsm4(a0, a1, a2, a3, abase + 32 * q);
                const uint2* wp = (const uint2*)Wu + ((nj * 32 + q) * 3) * 32 + lane;
                uint2 f0 = wp[0];
                uint2 f1 = wp[32];
                uint2 f2 = wp[64];
                const int p = q & 1;
                mma16(d[0][p], a0, a1, a2, a3, f0.x, f0.y);
                mma16(d[1][p], a0, a1, a2, a3, f1.x, f1.y);
                mma16(d[2][p], a0, a1, a2, a3, f2.x, f2.y);
            }
            // epilogue in registers — no smem handoff
            if (live0) {
                float gr0 = d[0][0][0] + d[0][1][0], gr1 = d[0][0][1] + d[0][1][1];
                float gz0 = d[1][0][0] + d[1][1][0], gz1 = d[1][0][1] + d[1][1][1];
                float gn0 = d[2][0][0] + d[2][1][0], gn1 = d[2][0][1] + d[2][1][1];
                float rr0 = sigm_(xr0.x + gr0 + br_.x);
                float rr1 = sigm_(xr0.y + gr1 + br_.y);
                float zz0 = sigm_(xz0.x + gz0 + bz_.x);
                float zz1 = sigm_(xz0.y + gz1 + bz_.y);
                float nn0 = tanhf(xn0.x + rr0 * (gn0 + bn_.x));
                float nn1 = tanhf(xn0.y + rr1 * (gn1 + bn_.y));
                float h0 = (1.f - zz0) * nn0 + zz0 * hold[0];
                float h1 = (1.f - zz1) * nn1 + zz1 * hold[1];
                hold[0] = h0; hold[1] = h1;
                float2 hv = make_float2(h0, h1);
                *(float2*)(out + OUT_RFTS + (size_t)(row0 + t) * HDIM + kglob) = hv;
                *(float2*)(hn + (size_t)b30 * HDIM + kglob) = hv;
            }
            if (live1) {
                float gr0 = d[0][0][2] + d[0][1][2], gr1 = d[0][0][3] + d[0][1][3];
                float gz0 = d[1][0][2] + d[1][1][2], gz1 = d[1][0][3] + d[1][1][3];
                float gn0 = d[2][0][2] + d[2][1][2], gn1 = d[2][0][3] + d[2][1][3];
                float rr0 = sigm_(xr1.x + gr0 + br_.x);
                float rr1 = sigm_(xr1.y + gr1 + br_.y);
                float zz0 = sigm_(xz1.x + gz0 + bz_.x);
                float zz1 = sigm_(xz1.y + gz1 + bz_.y);
                float nn0 = tanhf(xn1.x + rr0 * (gn0 + bn_.x));
                float nn1 = tanhf(xn1.y + rr1 * (gn1 + bn_.y));
                float h0 = (1.f - zz0) * nn0 + zz0 * hold[2];
                float h1 = (1.f - zz1) * nn1 + zz1 * hold[3];
                hold[2] = h0; hold[3] = h1;
                float2 hv = make_float2(h0, h1);
                *(float2*)(out + OUT_RFTS + (size_t)(row1 + t) * HDIM + kglob) = hv;
                *(float2*)(hn + (size_t)b31 * HDIM + kglob) = hv;
            }
        }

        // inter-CTA barrier: release/acquire
        __syncthreads();
        if (tid == 0) {
            int a;
            asm volatile("atom.acq_rel.gpu.global.add.s32 %0, [%1], 1;"
                         : "=r"(a) : "l"(cntp) : "memory");
            if (a == NKG - 1) {
                asm volatile("st.relaxed.gpu.global.s32 [%0], %1;"
                             :: "l"(cntp), "r"(0) : "memory");
                asm volatile("st.release.gpu.global.s32 [%0], %1;"
                             :: "l"(genp), "r"(t + 1) : "memory");
            } else {
                int g;
                do {
                    asm volatile("ld.acquire.gpu.global.s32 %0, [%1];"
                                 : "=r"(g) : "l"(genp) : "memory");
                } while (g <= t);
            }
        }
        __syncthreads();
    }

    if (b30 >= 0)
        *(float2*)(out + OUT_HIDS + (size_t)b30 * HDIM + kglob) = make_float2(hold[0], hold[1]);
    if (b31 >= 0)
        *(float2*)(out + OUT_HIDS + (size_t)b31 * HDIM + kglob) = make_float2(hold[2], hold[3]);
}

// ---------------- packing & masks ----------------
__global__ void msks_kernel(float* __restrict__ out) {
    int b = blockIdx.x, t = threadIdx.x;
    out[OUT_MSKS + (size_t)b * TT + t] = (t < g_tlen[b]) ? 1.f : 0.f;
}

__global__ void pack_emb_kernel(const int* __restrict__ inds,
                                const float* __restrict__ emb,
                                float* __restrict__ out) {
    int t = blockIdx.x, b3 = blockIdx.y;
    if (t >= g_len[b3]) return;
    int tok = inds[b3 * SLEN + t];
    size_t row = (size_t)(b3 / 3) * TT + g_off[b3] + t;
    if (threadIdx.x < 75) {
        float4 v = *(const float4*)(emb + (size_t)tok * EDIM + threadIdx.x * 4);
        *(float4*)(out + OUT_EMBS + row * EDIM + threadIdx.x * 4) = v;
    }
}

// ---------------- GCN GEMM ----------------
__global__ __launch_bounds__(256)
void gemm64_kernel(const float* __restrict__ A, const float* __restrict__ B,
                   float* __restrict__ C, int M, int N, int K) {
    const int BK = 8;
    int m0 = blockIdx.y * 64, n0 = blockIdx.x * 64;
    __shared__ float As[BK * 64];
    __shared__ float Bs[BK * 64];
    int tid = threadIdx.x;
    int tx = tid & 15, ty = tid >> 4;

    float acc[4][4];
#pragma unroll
    for (int i = 0; i < 4; i++)
#pragma unroll
        for (int j = 0; j < 4; j++) acc[i][j] = 0.f;

    for (int k0 = 0; k0 < K; k0 += BK) {
#pragma unroll
        for (int i = 0; i < 2; i++) {
            int idx = tid + i * 256;
            int r = idx / BK, e = idx % BK;
            float v = 0.f;
            if (m0 + r < M) v = A[(size_t)(m0 + r) * K + k0 + e];
            As[e * 64 + r] = v;
        }
#pragma unroll
        for (int i = 0; i < 2; i++) {
            int idx = tid + i * 256;
            int e = idx >> 6, n = idx & 63;
            float v = 0.f;
            if (n0 + n < N) v = B[(size_t)(k0 + e) * N + n0 + n];
            Bs[e * 64 + n] = v;
        }
        __syncthreads();
#pragma unroll
        for (int e = 0; e < BK; e++) {
            float4 a = *(const float4*)&As[e * 64 + ty * 4];
            float4 b = *(const float4*)&Bs[e * 64 + tx * 4];
            acc[0][0] = fmaf(a.x, b.x, acc[0][0]); acc[0][1] = fmaf(a.x, b.y, acc[0][1]);
            acc[0][2] = fmaf(a.x, b.z, acc[0][2]); acc[0][3] = fmaf(a.x, b.w, acc[0][3]);
            acc[1][0] = fmaf(a.y, b.x, acc[1][0]); acc[1][1] = fmaf(a.y, b.y, acc[1][1]);
            acc[1][2] = fmaf(a.y, b.z, acc[1][2]); acc[1][3] = fmaf(a.y, b.w, acc[1][3]);
            acc[2][0] = fmaf(a.z, b.x, acc[2][0]); acc[2][1] = fmaf(a.z, b.y, acc[2][1]);
            acc[2][2] = fmaf(a.z, b.z, acc[2][2]); acc[2][3] = fmaf(a.z, b.w, acc[2][3]);
            acc[3][0] = fmaf(a.w, b.x, acc[3][0]); acc[3][1] = fmaf(a.w, b.y, acc[3][1]);
            acc[3][2] = fmaf(a.w, b.z, acc[3][2]); acc[3][3] = fmaf(a.w, b.w, acc[3][3]);
        }
        __syncthreads();
    }
#pragma unroll
    for (int i = 0; i < 4; i++) {
        int rg = m0 + ty * 4 + i;
        if (rg >= M) continue;
#pragma unroll
        for (int j = 0; j < 4; j++) {
            int cg = n0 + tx * 4 + j;
            if (cg < N) C[(size_t)rg * N + cg] = acc[i][j];
        }
    }
}

__global__ void adjmul_kernel(const float* __restrict__ adj, const float* __restrict__ X,
                              const float* __restrict__ bias, float* __restrict__ Y,
                              int F, int relu) {
    int total = BS * NNODE * F;
    for (int idx = blockIdx.x * blockDim.x + threadIdx.x; idx < total;
         idx += gridDim.x * blockDim.x) {
        int f = idx % F;
        int n = (idx / F) % NNODE;
        int b = idx / (F * NNODE);
        const float* Xb = X + (size_t)(b * NNODE) * F;
        const float* ad = adj + (size_t)(b * NNODE + n) * NNODE;
        float acc = bias[f];
#pragma unroll
        for (int m = 0; m < NNODE; m++)
            acc = fmaf(ad[m], Xb[(size_t)m * F + f], acc);
        if (relu) acc = fmaxf(acc, 0.f);
        Y[idx] = acc;
    }
}

// ---------------- host ----------------
extern "C" void kernel_launch(void* const* d_in, const int* in_sizes, int n_in,
                              void* d_out, int out_size) {
    const int*   inds = (const int*)  d_in[0];
    const int*   lens = (const int*)  d_in[1];
    const float* emb  = (const float*)d_in[2];
    const float* w_ih = (const float*)d_in[3];
    const float* w_hh = (const float*)d_in[4];
    const float* b_ih = (const float*)d_in[5];
    const float* b_hh = (const float*)d_in[6];
    const float* sg_x = (const float*)d_in[7];
    const float* adj  = (const float*)d_in[8];
    const float* gw1  = (const float*)d_in[9];
    const float* gb1  = (const float*)d_in[10];
    const float* gw2  = (const float*)d_in[11];
    const float* gb2  = (const float*)d_in[12];
    float* out = (float*)d_out;

    cudaFuncSetAttribute(gru_mma_kernel,
                         cudaFuncAttributeMaxDynamicSharedMemorySize, GRU_SMEM_BYTES);

    cudaMemsetAsync(d_out, 0, (size_t)out_size * sizeof(float), 0);
    zero_h_kernel<<<(B3 * HDIM + 511) / 512, 512>>>();
    prep_kernel<<<1, 256>>>(lens);

    xi_mma_kernel<<<dim3(G3 / 128, (B3 * SLEN) / YBM), 256>>>(inds, emb, w_ih, b_ih);

    msks_kernel<<<BS, TT>>>(out);
    pack_emb_kernel<<<dim3(SLEN, B3), 96>>>(inds, emb, out);

    gru_mma_kernel<<<dim3(NKG, NBG), 256, GRU_SMEM_BYTES>>>(w_hh, b_hh, out);

    // GCN
    gemm64_kernel<<<dim3((NHID + 63) / 64, (BN + 63) / 64), 256>>>(sg_x, gw1, g_t1, BN, NHID, NFEAT);
    adjmul_kernel<<<1350, 512>>>(adj, g_t1, gb1, g_h1, NHID, 1);
    gemm64_kernel<<<dim3((NOUT + 63) / 64, (BN + 63) / 64), 256>>>(g_h1, gw2, g_t2, BN, NOUT, NHID);
    adjmul_kernel<<<2304, 512>>>(adj, g_t2, gb2, out + OUT_SG, NOUT, 0);
}